// round 11
// baseline (speedup 1.0000x reference)
#include <cuda_runtime.h>
#include <cstdint>

namespace {
constexpr int kB = 16, kH = 256, kC = 128, kW = 128;
constexpr long kCC = (long)kC * kC;
}

// Scratch (device globals: allocation-free contract).
__device__ float g_q[(size_t)kB * kW * kH * kC];   // q (B,W,H,C); reused as m5 (B,W,C,H)
__device__ float g_k[(size_t)kB * kW * kH * kC];   // k (B,W,H,C); reused as m6 (B,H,C,W)
__device__ float g_v[(size_t)kB * kW * kH * kC];   // v (B,W,H,C)
__device__ float g_s[(size_t)kB * kW * kC * kC];   // exp(scores) (B,W,D,C)
__device__ float g_inv[(size_t)kB * kC * kC];      // 1/sum_w exp (B,D,C)

__device__ __forceinline__ uint32_t smem_u32(const void* p) {
  uint32_t a;
  asm("{ .reg .u64 t; cvta.to.shared.u64 t, %1; cvt.u32.u64 %0, t; }" : "=r"(a) : "l"(p));
  return a;
}
__device__ __forceinline__ uint32_t f2tf32(float f) {
  uint32_t r;
  asm("cvt.rna.tf32.f32 %0, %1;" : "=r"(r) : "f"(f));
  return r;
}
__device__ __forceinline__ void cpa16(uint32_t dst, const void* src) {
  asm volatile("cp.async.cg.shared.global [%0], [%1], 16;" :: "r"(dst), "l"(src));
}
__device__ __forceinline__ void cpa_commit() {
  asm volatile("cp.async.commit_group;" ::: "memory");
}
__device__ __forceinline__ void cpa_wait1() {
  asm volatile("cp.async.wait_group 1;" ::: "memory");
}
__device__ __forceinline__ void cpa_wait0() {
  asm volatile("cp.async.wait_group 0;" ::: "memory");
}

// exp on the FMA pipe (no MUFU): exp(x) = 2^r * e^f, deg-5 Taylor on |f|<=ln2/2.
__device__ __forceinline__ float fast_exp(float x) {
  x = fminf(fmaxf(x, -30.f), 30.f);
  float r = rintf(x * 1.44269504f);
  float f = fmaf(r, -0.6931471805599453f, x);
  float p = 1.f + f * (1.f + f * (0.5f + f * (0.16666667f +
                f * (0.041666667f + f * 0.0083333333f))));
  return p * __int_as_float(((int)r + 127) << 23);
}

// SMEM row stride (words). 36 => ldmatrix phases span all 32 banks (4r+c).
constexpr int kLds = 36;
constexpr int kBufW = 128 * kLds;   // words per stage (4608)
constexpr int kWnS = 132;           // wn smem row stride (132 % 32 == 4)
constexpr int kWnWords = 128 * kWnS;  // 16896

// Load 16 k-words of one row into registers. KC=true: k unit stride (float4).
template <bool KC>
__device__ __forceinline__ void ldg16(float4 r[4], const float* __restrict__ p, long sK) {
  if (KC) {
#pragma unroll
    for (int i = 0; i < 4; i++) r[i] = reinterpret_cast<const float4*>(p)[i];
  } else {
#pragma unroll
    for (int i = 0; i < 4; i++) {
      r[i].x = p[(long)(i * 4 + 0) * sK];
      r[i].y = p[(long)(i * 4 + 1) * sK];
      r[i].z = p[(long)(i * 4 + 2) * sK];
      r[i].w = p[(long)(i * 4 + 3) * sK];
    }
  }
}

// Convert to tf32 (optionally *nrm first) and store 16 contiguous words to smem.
template <bool NORM>
__device__ __forceinline__ void sts16(uint32_t* __restrict__ dst, const float4 a[4],
                                      const float4 n[4]) {
#pragma unroll
  for (int i = 0; i < 4; i++) {
    float4 v = a[i];
    if (NORM) {
      v.x *= n[i].x; v.y *= n[i].y; v.z *= n[i].z; v.w *= n[i].w;
    }
    uint32_t t0 = f2tf32(v.x), t1 = f2tf32(v.y), t2 = f2tf32(v.z), t3 = f2tf32(v.w);
    asm volatile("st.shared.v4.b32 [%0], {%1,%2,%3,%4};"
                 :: "l"(dst + i * 4), "r"(t0), "r"(t1), "r"(t2), "r"(t3));
  }
}

// Direct gmem -> smem (short-lived register temps only).
template <bool KC, bool NORM>
__device__ __forceinline__ void load_store16(uint32_t* __restrict__ dst,
                                             const float* __restrict__ src, long sK,
                                             const float* __restrict__ nsrc) {
  float4 a[4], n[4];
  ldg16<KC>(a, src, sK);
  if (NORM) ldg16<KC>(n, nsrc, sK);
  sts16<NORM>(dst, a, n);
}

__device__ __forceinline__ void ldsm_x4(uint32_t r[4], uint32_t addr) {
  asm volatile("ldmatrix.sync.aligned.m8n8.x4.shared.b16 {%0,%1,%2,%3}, [%4];"
               : "=r"(r[0]), "=r"(r[1]), "=r"(r[2]), "=r"(r[3]) : "r"(addr));
}

// Per-lane byte offsets for ldmatrix.x4.
__device__ __forceinline__ uint32_t a4_off(int lane, int stride) {
  return (uint32_t)(((((lane & 7) + ((lane >> 3) & 1) * 8) * stride) + (lane >> 4) * 4) * 4);
}
__device__ __forceinline__ uint32_t b4_off(int lane, int stride) {
  return (uint32_t)(((((lane & 7) + ((lane >> 4) & 1) * 8) * stride) + ((lane >> 3) & 1) * 4) * 4);
}

__device__ __forceinline__ void mma_tf32(float acc[4], const uint32_t a[4],
                                         const uint32_t b[2]) {
  asm volatile(
      "mma.sync.aligned.m16n8k8.row.col.f32.tf32.tf32.f32 "
      "{%0,%1,%2,%3}, {%4,%5,%6,%7}, {%8,%9}, {%0,%1,%2,%3};"
      : "+f"(acc[0]), "+f"(acc[1]), "+f"(acc[2]), "+f"(acc[3])
      : "r"(a[0]), "r"(a[1]), "r"(a[2]), "r"(a[3]), "r"(b[0]), "r"(b[1]));
}

// One ks-step of the 64x32 warp tile. CVTA: round A frags to tf32 in regs
// (for raw-fp32 smem filled by cp.async).
template <bool CVTA>
__device__ __forceinline__ void warp_mma_step(float acc[4][4][4], uint32_t aBase,
                                              uint32_t bBase, int ks, int strideB) {
  uint32_t af[4][4], bf[4][2];
#pragma unroll
  for (int im = 0; im < 4; im++) {
    ldsm_x4(af[im], aBase + (uint32_t)((im * 16 * kLds + ks * 8) * 4));
    if (CVTA) {
#pragma unroll
      for (int j = 0; j < 4; j++) af[im][j] = f2tf32(__uint_as_float(af[im][j]));
    }
  }
  {
    uint32_t bt[4];
    ldsm_x4(bt, bBase + (uint32_t)((ks * 8) * 4));
    bf[0][0] = bt[0]; bf[0][1] = bt[1]; bf[1][0] = bt[2]; bf[1][1] = bt[3];
    ldsm_x4(bt, bBase + (uint32_t)((16 * strideB + ks * 8) * 4));
    bf[2][0] = bt[0]; bf[2][1] = bt[1]; bf[3][0] = bt[2]; bf[3][1] = bt[3];
  }
#pragma unroll
  for (int im = 0; im < 4; im++)
#pragma unroll
    for (int in = 0; in < 4; in++) mma_tf32(acc[im][in], af[im], bf[in]);
}

// Core 128x128 GEMM body via mma.sync tf32 (fp32 accumulate).
template <bool AKC, bool BKC, bool NORM, bool EEPI>
__device__ __forceinline__ void gemm_body(
    const float* __restrict__ A, long sAm, long sAk,
    const float* __restrict__ Bp, long sBn, long sBk,
    float* __restrict__ Cp, long sCn,
    const float* __restrict__ nrm,
    const float* __restrict__ bias_m, const float* __restrict__ bias_n,
    float alpha, int K) {
  __shared__ uint32_t As[2][kBufW];
  __shared__ uint32_t Bs[2][kBufW];
  __shared__ float bmS[128], bnS[128];

  const int tid = threadIdx.x;
  const int lane = tid & 31, wid = tid >> 5;
  const int wm = (wid & 1) * 64, wn = (wid >> 1) * 32;
  const int row = tid >> 1, khalf = (tid & 1) * 16;

  if (!EEPI && tid < 128) {
    bmS[tid] = bias_m ? bias_m[tid] : 0.f;
    bnS[tid] = bias_n ? bias_n[tid] : 0.f;
  }

  const float* Arow = A + (long)row * sAm + (long)khalf * sAk;
  const float* Brow = Bp + (long)row * sBn + (long)khalf * sBk;
  const float* Nrow = NORM ? nrm + (long)row * sAm + (long)khalf * sAk : nullptr;
  uint32_t* const sA = &As[0][0] + row * kLds + khalf;
  uint32_t* const sB = &Bs[0][0] + row * kLds + khalf;

  const uint32_t saA0 = smem_u32(As) + (uint32_t)(wm * kLds * 4) + a4_off(lane, kLds);
  const uint32_t saB0 = smem_u32(Bs) + (uint32_t)(wn * kLds * 4) + b4_off(lane, kLds);

  load_store16<AKC, NORM>(sA, Arow, sAk, Nrow);
  load_store16<BKC, false>(sB, Brow, sBk, nullptr);
  __syncthreads();

  float acc[4][4][4];
#pragma unroll
  for (int i = 0; i < 4; i++)
#pragma unroll
    for (int j = 0; j < 4; j++)
#pragma unroll
      for (int c = 0; c < 4; c++) acc[i][j][c] = 0.f;

  const int nch = K >> 5;
  for (int c = 0; c < nch; c++) {
    const uint32_t stg = (uint32_t)((c & 1) * kBufW * 4);
#pragma unroll
    for (int ks = 0; ks < 4; ks++)
      warp_mma_step<false>(acc, saA0 + stg, saB0 + stg, ks, kLds);
    if (c + 1 < nch) {
      const int nb = (c + 1) & 1;
      const long ko = (long)(c + 1) * 32;
      load_store16<AKC, NORM>(sA + nb * kBufW, Arow + ko * sAk, sAk,
                              NORM ? Nrow + ko * sAk : nullptr);
      load_store16<BKC, false>(sB + nb * kBufW, Brow + ko * sBk, sBk, nullptr);
    }
    __syncthreads();
  }

  const int g = lane >> 2, t2 = (lane & 3) * 2;
#pragma unroll
  for (int im = 0; im < 4; im++) {
    int m0 = wm + im * 16 + g;
    int m1 = m0 + 8;
    float bm0 = EEPI ? 0.f : bmS[m0], bm1 = EEPI ? 0.f : bmS[m1];
#pragma unroll
    for (int in = 0; in < 4; in++) {
      int n0 = wn + in * 8 + t2;
      int n1 = n0 + 1;
      if (EEPI) {
        Cp[(long)n0 * sCn + m0] = fast_exp(alpha * acc[im][in][0]);
        Cp[(long)n1 * sCn + m0] = fast_exp(alpha * acc[im][in][1]);
        Cp[(long)n0 * sCn + m1] = fast_exp(alpha * acc[im][in][2]);
        Cp[(long)n1 * sCn + m1] = fast_exp(alpha * acc[im][in][3]);
      } else {
        float bn0 = bnS[n0], bn1 = bnS[n1];
        Cp[(long)n0 * sCn + m0] = alpha * acc[im][in][0] + bm0 + bn0;
        Cp[(long)n1 * sCn + m0] = alpha * acc[im][in][1] + bm0 + bn1;
        Cp[(long)n0 * sCn + m1] = alpha * acc[im][in][2] + bm1 + bn0;
        Cp[(long)n1 * sCn + m1] = alpha * acc[im][in][3] + bm1 + bn1;
      }
    }
  }
}

// Projection kernel: grid.y selects operand set 0 or 1.
__global__ __launch_bounds__(256, 2) void gemm_proj(
    const float* __restrict__ x,
    const float* __restrict__ W0, const float* __restrict__ b0, float* __restrict__ o0,
    const float* __restrict__ W1, const float* __restrict__ b1, float* __restrict__ o1) {
  const int z = blockIdx.z, y = blockIdx.y;
  const float* A = (y == 0) ? W0 : W1;
  const float* bm = (y == 0) ? b0 : b1;
  float* C = ((y == 0) ? o0 : o1) +
             (long)(z / kH) * ((long)kW * kH * kC) + (long)(z % kH) * kC;
  const float* B = x + (long)z * kC * kW;
  gemm_body<false, false, false, false>(A, 1, kC, B, 1, kW, C, (long)kH * kC,
                                        nullptr, bm, nullptr, 1.f, kC);
}

template <bool AKC, bool BKC, bool NORM, bool EEPI>
__global__ __launch_bounds__(256, 2) void gemm_gen(
    const float* __restrict__ A, int a_div, long a_so, long a_si, long sAm, long sAk,
    const float* __restrict__ Bp, int b_div, long b_so, long b_si, long sBn, long sBk,
    float* __restrict__ Cp, int c_div, long c_so, long c_si, long sCn,
    const float* __restrict__ nrm_base, int nrm_div,
    const float* __restrict__ bias_m, const float* __restrict__ bias_n,
    float alpha, int K) {
  const int z = blockIdx.z, bx = blockIdx.x, by = blockIdx.y;
  A += (long)(z / a_div) * a_so + (long)(z % a_div) * a_si + (long)bx * 128 * sAm;
  Bp += (long)(z / b_div) * b_so + (long)(z % b_div) * b_si + (long)by * 128 * sBn;
  Cp += (long)(z / c_div) * c_so + (long)(z % c_div) * c_si + (long)bx * 128 +
        (long)by * 128 * sCn;
  const float* nrm = nullptr;
  if (NORM) nrm = nrm_base + (long)(z / nrm_div) * kCC + (long)bx * 128 * sAm;
  gemm_body<AKC, BKC, NORM, EEPI>(A, sAm, sAk, Bp, sBn, sBk, Cp, sCn, nrm,
                                  bias_m ? bias_m + bx * 128 : nullptr,
                                  bias_n ? bias_n + by * 128 : nullptr, alpha, K);
}

// Fused pass4+pass5 per z=(b,w). GEMM1 -> wn in smem; GEMM2 reads wn from smem,
// A (v) streamed via cp.async double-buffer.
__global__ __launch_bounds__(256, 2) void gemm_p45(
    const float* __restrict__ s, const float* __restrict__ Wn,
    const float* __restrict__ inv, const float* __restrict__ v,
    const float* __restrict__ bn, float* __restrict__ m5) {
  extern __shared__ uint32_t dynS[];
  uint32_t* const SA = dynS;
  uint32_t* const SB = dynS + 2 * kBufW;
  uint32_t* const WNS = dynS + 2 * kBufW;  // alias of SB region (+ extension)
  __shared__ float bnS[128];

  const int tid = threadIdx.x;
  const int lane = tid & 31, wid = tid >> 5;
  const int wm = (wid & 1) * 64, wn = (wid >> 1) * 32;
  const int row = tid >> 1, khalf = (tid & 1) * 16;
  const int z = blockIdx.z;
  const int b = z >> 7;  // z = b*kW + w

  if (tid < 128) bnS[tid] = bn[tid];

  const float* Arow1 = s + (long)z * kCC + row + (long)khalf * kC;
  const float* Nrow1 = inv + (long)b * kCC + row + (long)khalf * kC;
  const float* Brow1 = Wn + row + (long)khalf * kC;
  uint32_t* const sAp = SA + row * kLds + khalf;
  uint32_t* const sBp = SB + row * kLds + khalf;
  const uint32_t sApAddr = smem_u32(sAp);

  const uint32_t saA0 = smem_u32(SA) + (uint32_t)(wm * kLds * 4) + a4_off(lane, kLds);
  const uint32_t saB0 = smem_u32(SB) + (uint32_t)(wn * kLds * 4) + b4_off(lane, kLds);

  load_store16<false, true>(sAp, Arow1, kC, Nrow1);
  load_store16<false, false>(sBp, Brow1, kC, nullptr);
  __syncthreads();

  float acc[4][4][4];
#pragma unroll
  for (int i = 0; i < 4; i++)
#pragma unroll
    for (int j = 0; j < 4; j++)
#pragma unroll
      for (int c = 0; c < 4; c++) acc[i][j][c] = 0.f;

  for (int c = 0; c < 4; c++) {
    const uint32_t stg = (uint32_t)((c & 1) * kBufW * 4);
#pragma unroll
    for (int ks = 0; ks < 4; ks++)
      warp_mma_step<false>(acc, saA0 + stg, saB0 + stg, ks, kLds);
    if (c + 1 < 4) {
      const int nb = (c + 1) & 1;
      const long ko = (long)(c + 1) * 32;
      load_store16<false, true>(sAp + nb * kBufW, Arow1 + ko * kC, kC, Nrow1 + ko * kC);
      load_store16<false, false>(sBp + nb * kBufW, Brow1 + ko * kC, kC, nullptr);
    }
    __syncthreads();
  }

  // Epilogue1: wn tile -> WNS[c*kWnS + e], tf32-rounded, +bn[e].
  const int g = lane >> 2, t2 = (lane & 3) * 2;
#pragma unroll
  for (int im = 0; im < 4; im++) {
    int m0 = wm + im * 16 + g;
    int m1 = m0 + 8;
#pragma unroll
    for (int in = 0; in < 4; in++) {
      int n0 = wn + in * 8 + t2;
      int n1 = n0 + 1;
      WNS[m0 * kWnS + n0] = f2tf32(acc[im][in][0] + bnS[n0]);
      WNS[m0 * kWnS + n1] = f2tf32(acc[im][in][1] + bnS[n1]);
      WNS[m1 * kWnS + n0] = f2tf32(acc[im][in][2] + bnS[n0]);
      WNS[m1 * kWnS + n1] = f2tf32(acc[im][in][3] + bnS[n1]);
    }
  }
  __syncthreads();

  // GEMM2: A[m=h, k=e] = v[z, h, e] (k unit stride -> cp.async); B from WNS.
  const float* vz = v + (long)z * kH * kC;
  float* const mz = m5 + (long)z * kC * kH;
  const uint32_t saB2 = smem_u32(WNS) + (uint32_t)(wn * kWnS * 4) + b4_off(lane, kWnS);

  for (int hh = 0; hh < 2; hh++) {
    const float* Arow2 = vz + (long)(hh * 128 + row) * kC + khalf;
    // Prologue: chunk 0 async into stage 0.
#pragma unroll
    for (int i = 0; i < 4; i++) cpa16(sApAddr + i * 16, Arow2 + i * 4);
    cpa_commit();

#pragma unroll
    for (int i = 0; i < 4; i++)
#pragma unroll
      for (int j = 0; j < 4; j++)
#pragma unroll
        for (int c = 0; c < 4; c++) acc[i][j][c] = 0.f;

    for (int c = 0; c < 4; c++) {
      if (c + 1 < 4) {
        const uint32_t d = sApAddr + (uint32_t)(((c + 1) & 1) * kBufW * 4);
        const float* src = Arow2 + (c + 1) * 32;
#pragma unroll
        for (int i = 0; i < 4; i++) cpa16(d + i * 16, src + i * 4);
        cpa_commit();
        cpa_wait1();
      } else {
        cpa_wait0();
      }
      __syncthreads();  // chunk c visible to all
      const uint32_t aBase = saA0 + (uint32_t)((c & 1) * kBufW * 4);
      const uint32_t bBase = saB2 + (uint32_t)((c * 32) * 4);
#pragma unroll
      for (int ks = 0; ks < 4; ks++)
        warp_mma_step<true>(acc, aBase, bBase, ks, kWnS);
      __syncthreads();  // all reads done before next cpa overwrites
    }

#pragma unroll
    for (int im = 0; im < 4; im++) {
      int m0 = hh * 128 + wm + im * 16 + g;
      int m1 = m0 + 8;
#pragma unroll
      for (int in = 0; in < 4; in++) {
        int n0 = wn + in * 8 + t2;
        int n1 = n0 + 1;
        mz[(long)n0 * kH + m0] = acc[im][in][0];
        mz[(long)n1 * kH + m0] = acc[im][in][1];
        mz[(long)n0 * kH + m1] = acc[im][in][2];
        mz[(long)n1 * kH + m1] = acc[im][in][3];
      }
    }
  }
}

// Per-(b,d,c) reciprocal of sum over w of exp(scores) stored in s (B,W,D,C).
__global__ __launch_bounds__(256) void softmax_sum(const float* __restrict__ s,
                                                   float* __restrict__ inv) {
  long t = (long)blockIdx.x * blockDim.x + threadIdx.x;  // < B*C*C
  int b = (int)(t / kCC);
  int r = (int)(t % kCC);
  const float* p = s + (long)b * kW * kCC + r;
  float l = 0.f;
#pragma unroll 8
  for (int w = 0; w < kW; w++) l += p[(long)w * kCC];
  inv[t] = 1.f / l;
}

// Transpose m5 (B,W,C,H) -> m6 (B,H,C,W).
__global__ __launch_bounds__(256) void trans_wh(const float* __restrict__ in,
                                                float* __restrict__ out) {
  __shared__ float tile[32][33];
  int bc = blockIdx.z;
  int b = bc / kC, c = bc % kC;
  long ibase = (long)b * kW * kC * kH + (long)c * kH;
  long obase = (long)b * kH * kC * kW + (long)c * kW;
  int w0 = blockIdx.x * 32, h0 = blockIdx.y * 32;
  int txl = threadIdx.x;
#pragma unroll
  for (int i = threadIdx.y; i < 32; i += 8)
    tile[i][txl] = in[ibase + (long)(w0 + i) * (kC * kH) + h0 + txl];
  __syncthreads();
#pragma unroll
  for (int i = threadIdx.y; i < 32; i += 8)
    out[obase + (long)(h0 + i) * (kC * kW) + w0 + txl] = tile[txl][i];
}

extern "C" void kernel_launch(void* const* d_in, const int* in_sizes, int n_in,
                              void* d_out, int out_size) {
  (void)in_sizes; (void)n_in; (void)out_size;
  const float* x  = (const float*)d_in[0];
  const float* Wq = (const float*)d_in[1];
  const float* bq = (const float*)d_in[2];
  const float* Wk = (const float*)d_in[3];
  const float* bk = (const float*)d_in[4];
  const float* Wv = (const float*)d_in[5];
  const float* bv = (const float*)d_in[6];
  const float* Wn = (const float*)d_in[7];
  const float* bn = (const float*)d_in[8];
  const float* Wo = (const float*)d_in[9];
  const float* bo = (const float*)d_in[10];
  float* out = (float*)d_out;

  float *q, *k, *v, *s, *inv;
  cudaGetSymbolAddress((void**)&q, g_q);
  cudaGetSymbolAddress((void**)&k, g_k);
  cudaGetSymbolAddress((void**)&v, g_v);
  cudaGetSymbolAddress((void**)&s, g_s);
  cudaGetSymbolAddress((void**)&inv, g_inv);

  // One-time stream/event setup (host objects only; no device allocation).
  static cudaStream_t sV = nullptr;
  static cudaEvent_t evFork = nullptr, evJoin = nullptr;
  if (!sV) {
    cudaStreamCreateWithFlags(&sV, cudaStreamNonBlocking);
    cudaEventCreateWithFlags(&evFork, cudaEventDisableTiming);
    cudaEventCreateWithFlags(&evJoin, cudaEventDisableTiming);
  }

  const long HC = (long)kH * kC;
  const long CW = (long)kC * kW;
  const long CC = kCC;

  // Fork: v-projection on side stream, overlapping p2 + p3.
  cudaEventRecord(evFork, 0);
  cudaStreamWaitEvent(sV, evFork, 0);
  gemm_proj<<<dim3(1, 1, kB * kH), 256, 0, sV>>>(x, Wv, bv, v, Wv, bv, v);

  // Pass 1 (qk): z=(b*H+h), y selects q/k. m=d, n=w, k=c.
  gemm_proj<<<dim3(1, 2, kB * kH), 256>>>(x, Wq, bq, q, Wk, bk, k);

  // Pass 2: s[b,w][c,d] = exp(sum_h q*k / sqrt(W)). z=(b*W+w). m=c, n=d, k=h.
  gemm_gen<false, false, false, true><<<dim3(1, 1, kB * kW), 256>>>(
      q, 1, HC, 0, 1, kC,
      k, 1, HC, 0, 1, kC,
      s, 1, CC, 0, kC,
      nullptr, 1, nullptr, nullptr, 0.08838834764831845f, kH);

  // Pass 3: softmax denominators.
  softmax_sum<<<(int)((kB * CC) / 256), 256>>>(s, inv);

  // Join: v must be ready before p45.
  cudaEventRecord(evJoin, sV);
  cudaStreamWaitEvent(0, evJoin, 0);

  // Pass 4+5 fused: wn in smem, m5 (B,W,C,H) into g_q.
  const int dynBytes = (2 * kBufW + kWnWords) * 4;
  cudaFuncSetAttribute(gemm_p45, cudaFuncAttributeMaxDynamicSharedMemorySize, dynBytes);
  gemm_p45<<<dim3(1, 1, kB * kW), 256, dynBytes>>>(s, Wn, inv, v, bn, q);

  // Pass 5.5: transpose m5 (B,W,C,H) -> m6 (B,H,C,W).
  trans_wh<<<dim3(kW / 32, kH / 32, kB * kC), dim3(32, 8)>>>(q, k);

  // Pass 6: out[b,h][w,o] = sum_c m6[c,w]*Wo[c,o] + bo[o]. m=w, n=o, k=c.
  gemm_gen<false, false, false, false><<<dim3(1, 1, kB * kH), 256>>>(
      k, 1, CW, 0, 1, kW,
      Wo, 1, 0, 0, 1, kC,
      out, 1, CW, 0, kW,
      nullptr, 1, nullptr, bo, 1.f, kC);
}

// round 13
// speedup vs baseline: 1.4303x; 1.4303x over previous
#include <cuda_runtime.h>
#include <cuda_fp16.h>
#include <cstdint>

namespace {
constexpr int kB = 16, kH = 256, kC = 128, kW = 128;
constexpr long kCC = (long)kC * kC;
}

// Scratch (device globals: allocation-free contract).
__device__ __half g_q[(size_t)kB * kW * kH * kC];  // q (B,W,H,C); reused m5 (B,W,C,H)
__device__ __half g_k[(size_t)kB * kW * kH * kC];  // k (B,W,H,C); reused m6 (B,H,C,W)
__device__ __half g_v[(size_t)kB * kW * kH * kC];  // v (B,W,H,C)
__device__ float g_s[(size_t)kB * kW * kC * kC];   // exp(scores) (B,W,D,C)
__device__ float g_inv[(size_t)kB * kC * kC];      // 1/sum_w exp (B,D,C)

__device__ __forceinline__ uint32_t smem_u32(const void* p) {
  uint32_t a;
  asm("{ .reg .u64 t; cvta.to.shared.u64 t, %1; cvt.u32.u64 %0, t; }" : "=r"(a) : "l"(p));
  return a;
}
__device__ __forceinline__ uint32_t f2tf32(float f) {
  uint32_t r;
  asm("cvt.rna.tf32.f32 %0, %1;" : "=r"(r) : "f"(f));
  return r;
}

// exp on the FMA pipe (no MUFU): exp(x) = 2^r * e^f, deg-5 Taylor on |f|<=ln2/2.
__device__ __forceinline__ float fast_exp(float x) {
  x = fminf(fmaxf(x, -30.f), 30.f);
  float r = rintf(x * 1.44269504f);
  float f = fmaf(r, -0.6931471805599453f, x);
  float p = 1.f + f * (1.f + f * (0.5f + f * (0.16666667f +
                f * (0.041666667f + f * 0.0083333333f))));
  return p * __int_as_float(((int)r + 127) << 23);
}

// SMEM row stride (words). 36 => ldmatrix phases span all 32 banks.
constexpr int kLds = 36;
constexpr int kBufW = 128 * kLds;     // words per stage (4608)
constexpr int kWnS = 132;             // wn smem row stride (132 % 32 == 4)
constexpr int kWnWords = 128 * kWnS;  // 16896

// Load 16 k-words of one row (float). KC=true: k unit stride (float4).
template <bool KC>
__device__ __forceinline__ void ldg16(float4 r[4], const float* __restrict__ p, long sK) {
  if (KC) {
#pragma unroll
    for (int i = 0; i < 4; i++) r[i] = reinterpret_cast<const float4*>(p)[i];
  } else {
#pragma unroll
    for (int i = 0; i < 4; i++) {
      r[i].x = p[(long)(i * 4 + 0) * sK];
      r[i].y = p[(long)(i * 4 + 1) * sK];
      r[i].z = p[(long)(i * 4 + 2) * sK];
      r[i].w = p[(long)(i * 4 + 3) * sK];
    }
  }
}

// Load 16 k-elements of one row, convert to tf32-bit words, store to smem.
// T=float: tf32-round (optionally *nrm first). T=__half: exact h2f then tf32
// (identity on fp16 values -> no extra rounding).
template <bool KC, bool NORM, typename T>
__device__ __forceinline__ void load_conv16(uint32_t* __restrict__ dst,
                                            const T* __restrict__ src, long sK,
                                            const float* __restrict__ nsrc) {
  uint32_t w[16];
  if constexpr (sizeof(T) == 4) {
    float4 a[4], n[4];
    ldg16<KC>(a, reinterpret_cast<const float*>(src), sK);
    if (NORM) ldg16<KC>(n, nsrc, sK);
#pragma unroll
    for (int i = 0; i < 4; i++) {
      float4 v = a[i];
      if (NORM) { v.x *= n[i].x; v.y *= n[i].y; v.z *= n[i].z; v.w *= n[i].w; }
      w[i * 4 + 0] = f2tf32(v.x); w[i * 4 + 1] = f2tf32(v.y);
      w[i * 4 + 2] = f2tf32(v.z); w[i * 4 + 3] = f2tf32(v.w);
    }
  } else {
    if constexpr (KC) {
      const uint4* p = reinterpret_cast<const uint4*>(src);
      uint4 u0 = p[0], u1 = p[1];
      uint32_t vv[8] = {u0.x, u0.y, u0.z, u0.w, u1.x, u1.y, u1.z, u1.w};
#pragma unroll
      for (int j = 0; j < 8; j++) {
        __half2 h2 = *reinterpret_cast<__half2*>(&vv[j]);
        float2 f = __half22float2(h2);
        w[2 * j + 0] = f2tf32(f.x);
        w[2 * j + 1] = f2tf32(f.y);
      }
    } else {
      const __half* p = reinterpret_cast<const __half*>(src);
#pragma unroll
      for (int i = 0; i < 16; i++) w[i] = f2tf32(__half2float(p[(long)i * sK]));
    }
  }
#pragma unroll
  for (int i = 0; i < 4; i++) {
    asm volatile("st.shared.v4.b32 [%0], {%1,%2,%3,%4};"
                 :: "l"(dst + i * 4), "r"(w[4 * i]), "r"(w[4 * i + 1]),
                    "r"(w[4 * i + 2]), "r"(w[4 * i + 3]));
  }
}

template <typename TC>
__device__ __forceinline__ void stC(TC* p, float v) {
  if constexpr (sizeof(TC) == 4) *reinterpret_cast<float*>(p) = v;
  else *reinterpret_cast<__half*>(p) = __float2half_rn(v);
}

__device__ __forceinline__ void ldsm_x4(uint32_t r[4], uint32_t addr) {
  asm volatile("ldmatrix.sync.aligned.m8n8.x4.shared.b16 {%0,%1,%2,%3}, [%4];"
               : "=r"(r[0]), "=r"(r[1]), "=r"(r[2]), "=r"(r[3]) : "r"(addr));
}

// Per-lane byte offsets for ldmatrix.x4.
__device__ __forceinline__ uint32_t a4_off(int lane, int stride) {
  return (uint32_t)(((((lane & 7) + ((lane >> 3) & 1) * 8) * stride) + (lane >> 4) * 4) * 4);
}
__device__ __forceinline__ uint32_t b4_off(int lane, int stride) {
  return (uint32_t)(((((lane & 7) + ((lane >> 4) & 1) * 8) * stride) + ((lane >> 3) & 1) * 4) * 4);
}

__device__ __forceinline__ void mma_tf32(float acc[4], const uint32_t a[4],
                                         const uint32_t b[2]) {
  asm volatile(
      "mma.sync.aligned.m16n8k8.row.col.f32.tf32.tf32.f32 "
      "{%0,%1,%2,%3}, {%4,%5,%6,%7}, {%8,%9}, {%0,%1,%2,%3};"
      : "+f"(acc[0]), "+f"(acc[1]), "+f"(acc[2]), "+f"(acc[3])
      : "r"(a[0]), "r"(a[1]), "r"(a[2]), "r"(a[3]), "r"(b[0]), "r"(b[1]));
}

// One ks-step of the 64x32 warp tile: A x4 loads, B x4-pair loads, 16 MMAs.
__device__ __forceinline__ void warp_mma_step(float acc[4][4][4], uint32_t aBase,
                                              uint32_t bBase, int ks, int strideB) {
  uint32_t af[4][4], bf[4][2];
#pragma unroll
  for (int im = 0; im < 4; im++)
    ldsm_x4(af[im], aBase + (uint32_t)((im * 16 * kLds + ks * 8) * 4));
  {
    uint32_t bt[4];
    ldsm_x4(bt, bBase + (uint32_t)((ks * 8) * 4));
    bf[0][0] = bt[0]; bf[0][1] = bt[1]; bf[1][0] = bt[2]; bf[1][1] = bt[3];
    ldsm_x4(bt, bBase + (uint32_t)((16 * strideB + ks * 8) * 4));
    bf[2][0] = bt[0]; bf[2][1] = bt[1]; bf[3][0] = bt[2]; bf[3][1] = bt[3];
  }
#pragma unroll
  for (int im = 0; im < 4; im++)
#pragma unroll
    for (int in = 0; in < 4; in++) mma_tf32(acc[im][in], af[im], bf[in]);
}

// Core 128x128 GEMM body via mma.sync tf32 (fp32 accumulate).
// Double-buffered smem; direct LDG->STS of chunk c+1 after MMA of chunk c;
// one __syncthreads per chunk. 2 CTAs/SM for cross-CTA overlap.
template <bool AKC, bool BKC, bool NORM, bool EEPI, typename TA, typename TB, typename TC>
__device__ __forceinline__ void gemm_body(
    const TA* __restrict__ A, long sAm, long sAk,
    const TB* __restrict__ Bp, long sBn, long sBk,
    TC* __restrict__ Cp, long sCn,
    const float* __restrict__ nrm,
    const float* __restrict__ bias_m, const float* __restrict__ bias_n,
    float alpha, int K) {
  __shared__ uint32_t As[2][kBufW];
  __shared__ uint32_t Bs[2][kBufW];
  __shared__ float bmS[128], bnS[128];

  const int tid = threadIdx.x;
  const int lane = tid & 31, wid = tid >> 5;
  const int wm = (wid & 1) * 64, wn = (wid >> 1) * 32;
  const int row = tid >> 1, khalf = (tid & 1) * 16;

  if (!EEPI && tid < 128) {
    bmS[tid] = bias_m ? bias_m[tid] : 0.f;
    bnS[tid] = bias_n ? bias_n[tid] : 0.f;
  }

  const TA* Arow = A + (long)row * sAm + (long)khalf * sAk;
  const TB* Brow = Bp + (long)row * sBn + (long)khalf * sBk;
  const float* Nrow = NORM ? nrm + (long)row * sAm + (long)khalf * sAk : nullptr;
  uint32_t* const sA = &As[0][0] + row * kLds + khalf;
  uint32_t* const sB = &Bs[0][0] + row * kLds + khalf;

  const uint32_t saA0 = smem_u32(As) + (uint32_t)(wm * kLds * 4) + a4_off(lane, kLds);
  const uint32_t saB0 = smem_u32(Bs) + (uint32_t)(wn * kLds * 4) + b4_off(lane, kLds);

  load_conv16<AKC, NORM, TA>(sA, Arow, sAk, Nrow);
  load_conv16<BKC, false, TB>(sB, Brow, sBk, nullptr);
  __syncthreads();

  float acc[4][4][4];
#pragma unroll
  for (int i = 0; i < 4; i++)
#pragma unroll
    for (int j = 0; j < 4; j++)
#pragma unroll
      for (int c = 0; c < 4; c++) acc[i][j][c] = 0.f;

  const int nch = K >> 5;
  for (int c = 0; c < nch; c++) {
    const uint32_t stg = (uint32_t)((c & 1) * kBufW * 4);
#pragma unroll
    for (int ks = 0; ks < 4; ks++)
      warp_mma_step(acc, saA0 + stg, saB0 + stg, ks, kLds);
    if (c + 1 < nch) {
      const int nb = (c + 1) & 1;
      const long ko = (long)(c + 1) * 32;
      load_conv16<AKC, NORM, TA>(sA + nb * kBufW, Arow + ko * sAk, sAk,
                                 NORM ? Nrow + ko * sAk : nullptr);
      load_conv16<BKC, false, TB>(sB + nb * kBufW, Brow + ko * sBk, sBk, nullptr);
    }
    __syncthreads();
  }

  const int g = lane >> 2, t2 = (lane & 3) * 2;
#pragma unroll
  for (int im = 0; im < 4; im++) {
    int m0 = wm + im * 16 + g;
    int m1 = m0 + 8;
    float bm0 = EEPI ? 0.f : bmS[m0], bm1 = EEPI ? 0.f : bmS[m1];
#pragma unroll
    for (int in = 0; in < 4; in++) {
      int n0 = wn + in * 8 + t2;
      int n1 = n0 + 1;
      if (EEPI) {
        stC(Cp + (long)n0 * sCn + m0, fast_exp(alpha * acc[im][in][0]));
        stC(Cp + (long)n1 * sCn + m0, fast_exp(alpha * acc[im][in][1]));
        stC(Cp + (long)n0 * sCn + m1, fast_exp(alpha * acc[im][in][2]));
        stC(Cp + (long)n1 * sCn + m1, fast_exp(alpha * acc[im][in][3]));
      } else {
        float bn0 = bnS[n0], bn1 = bnS[n1];
        stC(Cp + (long)n0 * sCn + m0, alpha * acc[im][in][0] + bm0 + bn0);
        stC(Cp + (long)n1 * sCn + m0, alpha * acc[im][in][1] + bm0 + bn1);
        stC(Cp + (long)n0 * sCn + m1, alpha * acc[im][in][2] + bm1 + bn0);
        stC(Cp + (long)n1 * sCn + m1, alpha * acc[im][in][3] + bm1 + bn1);
      }
    }
  }
}

// Fused QKV: grid (1, 3, B*H); y selects weight/bias/output; fp16 outputs.
__global__ __launch_bounds__(256, 2) void gemm_qkv(
    const float* __restrict__ x,
    const float* __restrict__ Wq, const float* __restrict__ Wk, const float* __restrict__ Wv,
    const float* __restrict__ bq, const float* __restrict__ bk, const float* __restrict__ bv,
    __half* __restrict__ q, __half* __restrict__ k, __half* __restrict__ v) {
  const int z = blockIdx.z, y = blockIdx.y;
  const float* A = (y == 0) ? Wq : (y == 1) ? Wk : Wv;
  const float* bm = (y == 0) ? bq : (y == 1) ? bk : bv;
  __half* C = ((y == 0) ? q : (y == 1) ? k : v) +
              (long)(z / kH) * ((long)kW * kH * kC) + (long)(z % kH) * kC;
  const float* B = x + (long)z * kC * kW;
  gemm_body<false, false, false, false, float, float, __half>(
      A, 1, kC, B, 1, kW, C, (long)kH * kC, nullptr, bm, nullptr, 1.f, kC);
}

template <bool AKC, bool BKC, bool NORM, bool EEPI, typename TA, typename TB, typename TC>
__global__ __launch_bounds__(256, 2) void gemm_gen(
    const TA* __restrict__ A, int a_div, long a_so, long a_si, long sAm, long sAk,
    const TB* __restrict__ Bp, int b_div, long b_so, long b_si, long sBn, long sBk,
    TC* __restrict__ Cp, int c_div, long c_so, long c_si, long sCn,
    const float* __restrict__ nrm_base, int nrm_div,
    const float* __restrict__ bias_m, const float* __restrict__ bias_n,
    float alpha, int K) {
  const int z = blockIdx.z, bx = blockIdx.x, by = blockIdx.y;
  A += (long)(z / a_div) * a_so + (long)(z % a_div) * a_si + (long)bx * 128 * sAm;
  Bp += (long)(z / b_div) * b_so + (long)(z % b_div) * b_si + (long)by * 128 * sBn;
  Cp += (long)(z / c_div) * c_so + (long)(z % c_div) * c_si + (long)bx * 128 +
        (long)by * 128 * sCn;
  const float* nrm = nullptr;
  if (NORM) nrm = nrm_base + (long)(z / nrm_div) * kCC + (long)bx * 128 * sAm;
  gemm_body<AKC, BKC, NORM, EEPI, TA, TB, TC>(
      A, sAm, sAk, Bp, sBn, sBk, Cp, sCn, nrm,
      bias_m ? bias_m + bx * 128 : nullptr,
      bias_n ? bias_n + by * 128 : nullptr, alpha, K);
}

// Fused pass4+pass5 per z=(b,w). GEMM1 (fp32 in) -> wn in smem (tf32);
// GEMM2: A = v (fp16, k unit stride), B = wn smem; out m5 fp16.
__global__ __launch_bounds__(256, 2) void gemm_p45(
    const float* __restrict__ s, const float* __restrict__ Wn,
    const float* __restrict__ inv, const __half* __restrict__ v,
    const float* __restrict__ bn, __half* __restrict__ m5) {
  extern __shared__ uint32_t dynS[];
  uint32_t* const SA = dynS;
  uint32_t* const SB = dynS + 2 * kBufW;
  uint32_t* const WNS = dynS + 2 * kBufW;  // alias of SB region (+ extension)
  __shared__ float bnS[128];

  const int tid = threadIdx.x;
  const int lane = tid & 31, wid = tid >> 5;
  const int wm = (wid & 1) * 64, wn = (wid >> 1) * 32;
  const int row = tid >> 1, khalf = (tid & 1) * 16;
  const int z = blockIdx.z;
  const int b = z >> 7;  // z = b*kW + w

  if (tid < 128) bnS[tid] = bn[tid];

  const float* Arow1 = s + (long)z * kCC + row + (long)khalf * kC;
  const float* Nrow1 = inv + (long)b * kCC + row + (long)khalf * kC;
  const float* Brow1 = Wn + row + (long)khalf * kC;
  uint32_t* const sAp = SA + row * kLds + khalf;
  uint32_t* const sBp = SB + row * kLds + khalf;

  const uint32_t saA0 = smem_u32(SA) + (uint32_t)(wm * kLds * 4) + a4_off(lane, kLds);
  const uint32_t saB0 = smem_u32(SB) + (uint32_t)(wn * kLds * 4) + b4_off(lane, kLds);

  load_conv16<false, true, float>(sAp, Arow1, kC, Nrow1);
  load_conv16<false, false, float>(sBp, Brow1, kC, nullptr);
  __syncthreads();

  float acc[4][4][4];
#pragma unroll
  for (int i = 0; i < 4; i++)
#pragma unroll
    for (int j = 0; j < 4; j++)
#pragma unroll
      for (int c = 0; c < 4; c++) acc[i][j][c] = 0.f;

  for (int c = 0; c < 4; c++) {
    const uint32_t stg = (uint32_t)((c & 1) * kBufW * 4);
#pragma unroll
    for (int ks = 0; ks < 4; ks++)
      warp_mma_step(acc, saA0 + stg, saB0 + stg, ks, kLds);
    if (c + 1 < 4) {
      const int nb = (c + 1) & 1;
      const long ko = (long)(c + 1) * 32;
      load_conv16<false, true, float>(sAp + nb * kBufW, Arow1 + ko * kC, kC,
                                      Nrow1 + ko * kC);
      load_conv16<false, false, float>(sBp + nb * kBufW, Brow1 + ko * kC, kC, nullptr);
    }
    __syncthreads();
  }

  // Epilogue1: wn tile -> WNS[c*kWnS + e], tf32-rounded, +bn[e].
  const int g = lane >> 2, t2 = (lane & 3) * 2;
#pragma unroll
  for (int im = 0; im < 4; im++) {
    int m0 = wm + im * 16 + g;
    int m1 = m0 + 8;
#pragma unroll
    for (int in = 0; in < 4; in++) {
      int n0 = wn + in * 8 + t2;
      int n1 = n0 + 1;
      WNS[m0 * kWnS + n0] = f2tf32(acc[im][in][0] + bnS[n0]);
      WNS[m0 * kWnS + n1] = f2tf32(acc[im][in][1] + bnS[n1]);
      WNS[m1 * kWnS + n0] = f2tf32(acc[im][in][2] + bnS[n0]);
      WNS[m1 * kWnS + n1] = f2tf32(acc[im][in][3] + bnS[n1]);
    }
  }
  __syncthreads();

  // GEMM2: A[m=h, k=e] = v[z, h, e] (fp16, k unit stride); B from WNS.
  const __half* vz = v + (long)z * kH * kC;
  __half* const mz = m5 + (long)z * kC * kH;
  const uint32_t saB2 = smem_u32(WNS) + (uint32_t)(wn * kWnS * 4) + b4_off(lane, kWnS);

  for (int hh = 0; hh < 2; hh++) {
    const __half* Arow2 = vz + (long)(hh * 128 + row) * kC + khalf;
    load_conv16<true, false, __half>(sAp, Arow2, 1, nullptr);
    __syncthreads();

#pragma unroll
    for (int i = 0; i < 4; i++)
#pragma unroll
      for (int j = 0; j < 4; j++)
#pragma unroll
        for (int c = 0; c < 4; c++) acc[i][j][c] = 0.f;

    for (int c = 0; c < 4; c++) {
      const uint32_t aBase = saA0 + (uint32_t)((c & 1) * kBufW * 4);
      const uint32_t bBase = saB2 + (uint32_t)((c * 32) * 4);
#pragma unroll
      for (int ks = 0; ks < 4; ks++)
        warp_mma_step(acc, aBase, bBase, ks, kWnS);
      if (c + 1 < 4) {
        const int nb = (c + 1) & 1;
        load_conv16<true, false, __half>(sAp + nb * kBufW, Arow2 + (c + 1) * 32, 1,
                                         nullptr);
      }
      __syncthreads();
    }

#pragma unroll
    for (int im = 0; im < 4; im++) {
      int m0 = hh * 128 + wm + im * 16 + g;
      int m1 = m0 + 8;
#pragma unroll
      for (int in = 0; in < 4; in++) {
        int n0 = wn + in * 8 + t2;
        int n1 = n0 + 1;
        mz[(long)n0 * kH + m0] = __float2half_rn(acc[im][in][0]);
        mz[(long)n1 * kH + m0] = __float2half_rn(acc[im][in][1]);
        mz[(long)n0 * kH + m1] = __float2half_rn(acc[im][in][2]);
        mz[(long)n1 * kH + m1] = __float2half_rn(acc[im][in][3]);
      }
    }
  }
}

// Per-(b,d,c) reciprocal of sum over w of exp(scores) stored in s (B,W,D,C).
__global__ __launch_bounds__(256) void softmax_sum(const float* __restrict__ s,
                                                   float* __restrict__ inv) {
  long t = (long)blockIdx.x * blockDim.x + threadIdx.x;  // < B*C*C
  int b = (int)(t / kCC);
  int r = (int)(t % kCC);
  const float* p = s + (long)b * kW * kCC + r;
  float l = 0.f;
#pragma unroll 8
  for (int w = 0; w < kW; w++) l += p[(long)w * kCC];
  inv[t] = 1.f / l;
}

// Transpose m5 (B,W,C,H) -> m6 (B,H,C,W), fp16.
__global__ __launch_bounds__(256) void trans_wh(const __half* __restrict__ in,
                                                __half* __restrict__ out) {
  __shared__ unsigned short tile[32][33];
  int bc = blockIdx.z;
  int b = bc / kC, c = bc % kC;
  long ibase = (long)b * kW * kC * kH + (long)c * kH;
  long obase = (long)b * kH * kC * kW + (long)c * kW;
  int w0 = blockIdx.x * 32, h0 = blockIdx.y * 32;
  int txl = threadIdx.x;
  const unsigned short* inu = reinterpret_cast<const unsigned short*>(in);
  unsigned short* outu = reinterpret_cast<unsigned short*>(out);
#pragma unroll
  for (int i = threadIdx.y; i < 32; i += 8)
    tile[i][txl] = inu[ibase + (long)(w0 + i) * (kC * kH) + h0 + txl];
  __syncthreads();
#pragma unroll
  for (int i = threadIdx.y; i < 32; i += 8)
    outu[obase + (long)(h0 + i) * (kC * kW) + w0 + txl] = tile[txl][i];
}

extern "C" void kernel_launch(void* const* d_in, const int* in_sizes, int n_in,
                              void* d_out, int out_size) {
  (void)in_sizes; (void)n_in; (void)out_size;
  const float* x  = (const float*)d_in[0];
  const float* Wq = (const float*)d_in[1];
  const float* bq = (const float*)d_in[2];
  const float* Wk = (const float*)d_in[3];
  const float* bk = (const float*)d_in[4];
  const float* Wv = (const float*)d_in[5];
  const float* bv = (const float*)d_in[6];
  const float* Wn = (const float*)d_in[7];
  const float* bn = (const float*)d_in[8];
  const float* Wo = (const float*)d_in[9];
  const float* bo = (const float*)d_in[10];
  float* out = (float*)d_out;

  __half *q, *k, *v;
  float *s, *inv;
  cudaGetSymbolAddress((void**)&q, g_q);
  cudaGetSymbolAddress((void**)&k, g_k);
  cudaGetSymbolAddress((void**)&v, g_v);
  cudaGetSymbolAddress((void**)&s, g_s);
  cudaGetSymbolAddress((void**)&inv, g_inv);

  const long HC = (long)kH * kC;
  const long CW = (long)kC * kW;
  const long CC = kCC;

  // Pass 1: fused Q/K/V projections (fp16 out). z=(b*H+h), y selects head.
  gemm_qkv<<<dim3(1, 3, kB * kH), 256>>>(x, Wq, Wk, Wv, bq, bk, bv, q, k, v);

  // Pass 2: s[b,w][c,d] = exp(sum_h q*k / sqrt(W)). z=(b*W+w). m=c, n=d, k=h.
  gemm_gen<false, false, false, true, __half, __half, float>
      <<<dim3(1, 1, kB * kW), 256>>>(
      q, 1, HC, 0, 1, kC,
      k, 1, HC, 0, 1, kC,
      s, 1, CC, 0, kC,
      nullptr, 1, nullptr, nullptr, 0.08838834764831845f, kH);

  // Pass 3: softmax denominators.
  softmax_sum<<<(int)((kB * CC) / 256), 256>>>(s, inv);

  // Pass 4+5 fused: wn in smem, m5 (B,W,C,H) fp16 into g_q.
  const int dynBytes = (2 * kBufW + kWnWords) * 4;
  cudaFuncSetAttribute(gemm_p45, cudaFuncAttributeMaxDynamicSharedMemorySize, dynBytes);
  gemm_p45<<<dim3(1, 1, kB * kW), 256, dynBytes>>>(s, Wn, inv, v, bn, q);

  // Pass 5.5: transpose m5 (B,W,C,H) -> m6 (B,H,C,W), fp16.
  trans_wh<<<dim3(kW / 32, kH / 32, kB * kC), dim3(32, 8)>>>(q, k);

  // Pass 6: out[b,h][w,o] = sum_c m6[c,w]*Wo[c,o] + bo[o]. m=w, n=o, k=c.
  gemm_gen<false, false, false, false, __half, float, float>
      <<<dim3(1, 1, kB * kH), 256>>>(
      k, 1, CW, 0, 1, kW,
      Wo, 1, 0, 0, 1, kC,
      out, 1, CW, 0, kW,
      nullptr, 1, nullptr, bo, 1.f, kC);
}

// round 14
// speedup vs baseline: 1.7965x; 1.2560x over previous
#include <cuda_runtime.h>
#include <cuda_fp16.h>
#include <cstdint>

namespace {
constexpr int kB = 16, kH = 256, kC = 128, kW = 128;
constexpr long kCC = (long)kC * kC;
}

// Scratch (device globals: allocation-free contract).
__device__ __half g_q[(size_t)kB * kW * kH * kC];  // q (B,W,H,C); reused m5 (B,W,C,H)
__device__ __half g_k[(size_t)kB * kW * kH * kC];  // k (B,W,H,C); reused m6 (B,H,C,W)
__device__ __half g_v[(size_t)kB * kW * kH * kC];  // v (B,W,H,C)
__device__ float g_s[(size_t)kB * kW * kC * kC];   // exp(scores) (B,W,D,C)
__device__ float g_inv[(size_t)kB * kC * kC];      // 1/sum_w exp (B,D,C)

__device__ __forceinline__ uint32_t smem_u32(const void* p) {
  uint32_t a;
  asm("{ .reg .u64 t; cvta.to.shared.u64 t, %1; cvt.u32.u64 %0, t; }" : "=r"(a) : "l"(p));
  return a;
}

// exp on the FMA pipe (no MUFU): exp(x) = 2^r * e^f, deg-5 Taylor on |f|<=ln2/2.
__device__ __forceinline__ float fast_exp(float x) {
  x = fminf(fmaxf(x, -30.f), 30.f);
  float r = rintf(x * 1.44269504f);
  float f = fmaf(r, -0.6931471805599453f, x);
  float p = 1.f + f * (1.f + f * (0.5f + f * (0.16666667f +
                f * (0.041666667f + f * 0.0083333333f))));
  return p * __int_as_float(((int)r + 127) << 23);
}

// SMEM strides (halves). 40: ldmatrix row segments (r*80B) hit 8 distinct
// 16B bank-groups covering all 32 banks. 136: same property (r*272B).
constexpr int kLdsH = 40;
constexpr int kBufH = 128 * kLdsH;      // halves per stage (5120)
constexpr int kWnSH = 136;              // wn smem row stride (halves)
constexpr int kWnHalves = 128 * kWnSH;  // 17408

__device__ __forceinline__ uint32_t h2u(__half2 h) {
  return *reinterpret_cast<uint32_t*>(&h);
}

// Load 16 k-words of one row (float). KC=true: k unit stride (float4).
template <bool KC>
__device__ __forceinline__ void ldg16(float4 r[4], const float* __restrict__ p, long sK) {
  if (KC) {
#pragma unroll
    for (int i = 0; i < 4; i++) r[i] = reinterpret_cast<const float4*>(p)[i];
  } else {
#pragma unroll
    for (int i = 0; i < 4; i++) {
      r[i].x = p[(long)(i * 4 + 0) * sK];
      r[i].y = p[(long)(i * 4 + 1) * sK];
      r[i].z = p[(long)(i * 4 + 2) * sK];
      r[i].w = p[(long)(i * 4 + 3) * sK];
    }
  }
}

// Load 16 k-elements of one row, as fp16, store 32 bytes to smem.
// T=float: convert (optionally *nrm first). T=half: bit-exact copy.
template <bool KC, bool NORM, typename T>
__device__ __forceinline__ void load_conv16h(__half* __restrict__ dst,
                                             const T* __restrict__ src, long sK,
                                             const float* __restrict__ nsrc) {
  uint32_t w[8];
  if constexpr (sizeof(T) == 4) {
    float4 a[4], n[4];
    ldg16<KC>(a, reinterpret_cast<const float*>(src), sK);
    if (NORM) ldg16<KC>(n, nsrc, sK);
#pragma unroll
    for (int i = 0; i < 4; i++) {
      float4 v = a[i];
      if (NORM) { v.x *= n[i].x; v.y *= n[i].y; v.z *= n[i].z; v.w *= n[i].w; }
      w[2 * i + 0] = h2u(__floats2half2_rn(v.x, v.y));
      w[2 * i + 1] = h2u(__floats2half2_rn(v.z, v.w));
    }
  } else {
    if constexpr (KC) {
      const uint4* p = reinterpret_cast<const uint4*>(src);
      uint4 u0 = p[0], u1 = p[1];
      w[0] = u0.x; w[1] = u0.y; w[2] = u0.z; w[3] = u0.w;
      w[4] = u1.x; w[5] = u1.y; w[6] = u1.z; w[7] = u1.w;
    } else {
      const unsigned short* p = reinterpret_cast<const unsigned short*>(src);
#pragma unroll
      for (int i = 0; i < 8; i++) {
        uint32_t lo = p[(long)(2 * i) * sK];
        uint32_t hi = p[(long)(2 * i + 1) * sK];
        w[i] = lo | (hi << 16);
      }
    }
  }
  const uint32_t d = smem_u32(dst);
  asm volatile("st.shared.v4.b32 [%0], {%1,%2,%3,%4};"
               :: "r"(d), "r"(w[0]), "r"(w[1]), "r"(w[2]), "r"(w[3]));
  asm volatile("st.shared.v4.b32 [%0], {%1,%2,%3,%4};"
               :: "r"(d + 16), "r"(w[4]), "r"(w[5]), "r"(w[6]), "r"(w[7]));
}

template <typename TC>
__device__ __forceinline__ void stC(TC* p, float v) {
  if constexpr (sizeof(TC) == 4) *reinterpret_cast<float*>(p) = v;
  else *reinterpret_cast<__half*>(p) = __float2half_rn(v);
}

__device__ __forceinline__ void ldsm_x4(uint32_t r[4], uint32_t addr) {
  asm volatile("ldmatrix.sync.aligned.m8n8.x4.shared.b16 {%0,%1,%2,%3}, [%4];"
               : "=r"(r[0]), "=r"(r[1]), "=r"(r[2]), "=r"(r[3]) : "r"(addr));
}

// Per-lane byte offsets for ldmatrix.x4 (SH = row stride in halves).
// A (m16 x k16): lanes 0-7 rows 0-7 k0, 8-15 rows 8-15 k0, 16-23 rows 0-7 k8,
// 24-31 rows 8-15 k8.
__device__ __forceinline__ uint32_t a4_off_h(int lane, int SH) {
  return (uint32_t)((((lane & 7) + ((lane >> 3) & 1) * 8) * SH * 2) + (lane >> 4) * 16);
}
// B (two n8 x k16 tiles): lanes 0-7 n0-7 k0, 8-15 n0-7 k8, 16-23 n8-15 k0,
// 24-31 n8-15 k8.
__device__ __forceinline__ uint32_t b4_off_h(int lane, int SH) {
  return (uint32_t)((((lane & 7) + ((lane >> 4) & 1) * 8) * SH * 2) +
                    ((lane >> 3) & 1) * 16);
}

__device__ __forceinline__ void mma_f16(float acc[4], const uint32_t a[4],
                                        const uint32_t b[2]) {
  asm volatile(
      "mma.sync.aligned.m16n8k16.row.col.f32.f16.f16.f32 "
      "{%0,%1,%2,%3}, {%4,%5,%6,%7}, {%8,%9}, {%0,%1,%2,%3};"
      : "+f"(acc[0]), "+f"(acc[1]), "+f"(acc[2]), "+f"(acc[3])
      : "r"(a[0]), "r"(a[1]), "r"(a[2]), "r"(a[3]), "r"(b[0]), "r"(b[1]));
}

// One K=16 step of the 64x32 warp tile: 4 A ldsm.x4, 2 B ldsm.x4, 16 MMAs.
__device__ __forceinline__ void warp_mma_step_h(float acc[4][4][4], uint32_t aBase,
                                                uint32_t bBase, int ks, int strideBh) {
  uint32_t af[4][4], bt0[4], bt1[4];
#pragma unroll
  for (int im = 0; im < 4; im++)
    ldsm_x4(af[im], aBase + (uint32_t)(im * 16 * kLdsH * 2 + ks * 32));
  ldsm_x4(bt0, bBase + (uint32_t)(ks * 32));
  ldsm_x4(bt1, bBase + (uint32_t)(16 * strideBh * 2 + ks * 32));
  uint32_t bf[4][2] = {{bt0[0], bt0[1]}, {bt0[2], bt0[3]},
                       {bt1[0], bt1[1]}, {bt1[2], bt1[3]}};
#pragma unroll
  for (int im = 0; im < 4; im++)
#pragma unroll
    for (int in = 0; in < 4; in++) mma_f16(acc[im][in], af[im], bf[in]);
}

// Core 128x128 GEMM body via mma.sync fp16 (fp32 accumulate).
// Double-buffered smem; direct LDG->STS of chunk c+1 after MMA of chunk c;
// one __syncthreads per chunk. 2 CTAs/SM for cross-CTA overlap.
template <bool AKC, bool BKC, bool NORM, bool EEPI, typename TA, typename TB, typename TC>
__device__ __forceinline__ void gemm_body(
    const TA* __restrict__ A, long sAm, long sAk,
    const TB* __restrict__ Bp, long sBn, long sBk,
    TC* __restrict__ Cp, long sCn,
    const float* __restrict__ nrm,
    const float* __restrict__ bias_m, const float* __restrict__ bias_n,
    float alpha, int K) {
  __shared__ __half As[2 * kBufH];
  __shared__ __half Bs[2 * kBufH];
  __shared__ float bmS[128], bnS[128];

  const int tid = threadIdx.x;
  const int lane = tid & 31, wid = tid >> 5;
  const int wm = (wid & 1) * 64, wn = (wid >> 1) * 32;
  const int row = tid >> 1, khalf = (tid & 1) * 16;

  if (!EEPI && tid < 128) {
    bmS[tid] = bias_m ? bias_m[tid] : 0.f;
    bnS[tid] = bias_n ? bias_n[tid] : 0.f;
  }

  const TA* Arow = A + (long)row * sAm + (long)khalf * sAk;
  const TB* Brow = Bp + (long)row * sBn + (long)khalf * sBk;
  const float* Nrow = NORM ? nrm + (long)row * sAm + (long)khalf * sAk : nullptr;
  __half* const sA = As + row * kLdsH + khalf;
  __half* const sB = Bs + row * kLdsH + khalf;

  const uint32_t saA0 = smem_u32(As) + (uint32_t)(wm * kLdsH * 2) + a4_off_h(lane, kLdsH);
  const uint32_t saB0 = smem_u32(Bs) + (uint32_t)(wn * kLdsH * 2) + b4_off_h(lane, kLdsH);

  load_conv16h<AKC, NORM, TA>(sA, Arow, sAk, Nrow);
  load_conv16h<BKC, false, TB>(sB, Brow, sBk, nullptr);
  __syncthreads();

  float acc[4][4][4];
#pragma unroll
  for (int i = 0; i < 4; i++)
#pragma unroll
    for (int j = 0; j < 4; j++)
#pragma unroll
      for (int c = 0; c < 4; c++) acc[i][j][c] = 0.f;

  const int nch = K >> 5;
  for (int c = 0; c < nch; c++) {
    const uint32_t stg = (uint32_t)((c & 1) * kBufH * 2);
#pragma unroll
    for (int ks = 0; ks < 2; ks++)
      warp_mma_step_h(acc, saA0 + stg, saB0 + stg, ks, kLdsH);
    if (c + 1 < nch) {
      const int nb = (c + 1) & 1;
      const long ko = (long)(c + 1) * 32;
      load_conv16h<AKC, NORM, TA>(sA + nb * kBufH, Arow + ko * sAk, sAk,
                                  NORM ? Nrow + ko * sAk : nullptr);
      load_conv16h<BKC, false, TB>(sB + nb * kBufH, Brow + ko * sBk, sBk, nullptr);
    }
    __syncthreads();
  }

  const int g = lane >> 2, t2 = (lane & 3) * 2;
#pragma unroll
  for (int im = 0; im < 4; im++) {
    int m0 = wm + im * 16 + g;
    int m1 = m0 + 8;
    float bm0 = EEPI ? 0.f : bmS[m0], bm1 = EEPI ? 0.f : bmS[m1];
#pragma unroll
    for (int in = 0; in < 4; in++) {
      int n0 = wn + in * 8 + t2;
      int n1 = n0 + 1;
      if (EEPI) {
        stC(Cp + (long)n0 * sCn + m0, fast_exp(alpha * acc[im][in][0]));
        stC(Cp + (long)n1 * sCn + m0, fast_exp(alpha * acc[im][in][1]));
        stC(Cp + (long)n0 * sCn + m1, fast_exp(alpha * acc[im][in][2]));
        stC(Cp + (long)n1 * sCn + m1, fast_exp(alpha * acc[im][in][3]));
      } else {
        float bn0 = bnS[n0], bn1 = bnS[n1];
        stC(Cp + (long)n0 * sCn + m0, alpha * acc[im][in][0] + bm0 + bn0);
        stC(Cp + (long)n1 * sCn + m0, alpha * acc[im][in][1] + bm0 + bn1);
        stC(Cp + (long)n0 * sCn + m1, alpha * acc[im][in][2] + bm1 + bn0);
        stC(Cp + (long)n1 * sCn + m1, alpha * acc[im][in][3] + bm1 + bn1);
      }
    }
  }
}

// Fused QKV: grid (1, 3, B*H); y selects weight/bias/output; fp16 outputs.
__global__ __launch_bounds__(256, 2) void gemm_qkv(
    const float* __restrict__ x,
    const float* __restrict__ Wq, const float* __restrict__ Wk, const float* __restrict__ Wv,
    const float* __restrict__ bq, const float* __restrict__ bk, const float* __restrict__ bv,
    __half* __restrict__ q, __half* __restrict__ k, __half* __restrict__ v) {
  const int z = blockIdx.z, y = blockIdx.y;
  const float* A = (y == 0) ? Wq : (y == 1) ? Wk : Wv;
  const float* bm = (y == 0) ? bq : (y == 1) ? bk : bv;
  __half* C = ((y == 0) ? q : (y == 1) ? k : v) +
              (long)(z / kH) * ((long)kW * kH * kC) + (long)(z % kH) * kC;
  const float* B = x + (long)z * kC * kW;
  gemm_body<false, false, false, false, float, float, __half>(
      A, 1, kC, B, 1, kW, C, (long)kH * kC, nullptr, bm, nullptr, 1.f, kC);
}

template <bool AKC, bool BKC, bool NORM, bool EEPI, typename TA, typename TB, typename TC>
__global__ __launch_bounds__(256, 2) void gemm_gen(
    const TA* __restrict__ A, int a_div, long a_so, long a_si, long sAm, long sAk,
    const TB* __restrict__ Bp, int b_div, long b_so, long b_si, long sBn, long sBk,
    TC* __restrict__ Cp, int c_div, long c_so, long c_si, long sCn,
    const float* __restrict__ nrm_base, int nrm_div,
    const float* __restrict__ bias_m, const float* __restrict__ bias_n,
    float alpha, int K) {
  const int z = blockIdx.z, bx = blockIdx.x, by = blockIdx.y;
  A += (long)(z / a_div) * a_so + (long)(z % a_div) * a_si + (long)bx * 128 * sAm;
  Bp += (long)(z / b_div) * b_so + (long)(z % b_div) * b_si + (long)by * 128 * sBn;
  Cp += (long)(z / c_div) * c_so + (long)(z % c_div) * c_si + (long)bx * 128 +
        (long)by * 128 * sCn;
  const float* nrm = nullptr;
  if (NORM) nrm = nrm_base + (long)(z / nrm_div) * kCC + (long)bx * 128 * sAm;
  gemm_body<AKC, BKC, NORM, EEPI, TA, TB, TC>(
      A, sAm, sAk, Bp, sBn, sBk, Cp, sCn, nrm,
      bias_m ? bias_m + bx * 128 : nullptr,
      bias_n ? bias_n + by * 128 : nullptr, alpha, K);
}

// Fused pass4+pass5 per z=(b,w). GEMM1 (fp32 in) -> wn in smem (fp16);
// GEMM2: A = v (fp16, k unit stride), B = wn smem; out m5 fp16.
__global__ __launch_bounds__(256, 2) void gemm_p45(
    const float* __restrict__ s, const float* __restrict__ Wn,
    const float* __restrict__ inv, const __half* __restrict__ v,
    const float* __restrict__ bn, __half* __restrict__ m5) {
  extern __shared__ __half dynH[];
  __half* const SA = dynH;
  __half* const SB = dynH + 2 * kBufH;
  __half* const WNS = dynH + 2 * kBufH;  // alias of SB region (+ extension)
  __shared__ float bnS[128];

  const int tid = threadIdx.x;
  const int lane = tid & 31, wid = tid >> 5;
  const int wm = (wid & 1) * 64, wn = (wid >> 1) * 32;
  const int row = tid >> 1, khalf = (tid & 1) * 16;
  const int z = blockIdx.z;
  const int b = z >> 7;  // z = b*kW + w

  if (tid < 128) bnS[tid] = bn[tid];

  const float* Arow1 = s + (long)z * kCC + row + (long)khalf * kC;
  const float* Nrow1 = inv + (long)b * kCC + row + (long)khalf * kC;
  const float* Brow1 = Wn + row + (long)khalf * kC;
  __half* const sAp = SA + row * kLdsH + khalf;
  __half* const sBp = SB + row * kLdsH + khalf;

  const uint32_t saA0 = smem_u32(SA) + (uint32_t)(wm * kLdsH * 2) + a4_off_h(lane, kLdsH);
  const uint32_t saB0 = smem_u32(SB) + (uint32_t)(wn * kLdsH * 2) + b4_off_h(lane, kLdsH);

  load_conv16h<false, true, float>(sAp, Arow1, kC, Nrow1);
  load_conv16h<false, false, float>(sBp, Brow1, kC, nullptr);
  __syncthreads();

  float acc[4][4][4];
#pragma unroll
  for (int i = 0; i < 4; i++)
#pragma unroll
    for (int j = 0; j < 4; j++)
#pragma unroll
      for (int c = 0; c < 4; c++) acc[i][j][c] = 0.f;

  for (int c = 0; c < 4; c++) {
    const uint32_t stg = (uint32_t)((c & 1) * kBufH * 2);
#pragma unroll
    for (int ks = 0; ks < 2; ks++)
      warp_mma_step_h(acc, saA0 + stg, saB0 + stg, ks, kLdsH);
    if (c + 1 < 4) {
      const int nb = (c + 1) & 1;
      const long ko = (long)(c + 1) * 32;
      load_conv16h<false, true, float>(sAp + nb * kBufH, Arow1 + ko * kC, kC,
                                       Nrow1 + ko * kC);
      load_conv16h<false, false, float>(sBp + nb * kBufH, Brow1 + ko * kC, kC, nullptr);
    }
    __syncthreads();
  }

  // Epilogue1: wn tile -> WNS[c*kWnSH + e] (fp16), +bn[e].
  const int g = lane >> 2, t2 = (lane & 3) * 2;
#pragma unroll
  for (int im = 0; im < 4; im++) {
    int m0 = wm + im * 16 + g;
    int m1 = m0 + 8;
#pragma unroll
    for (int in = 0; in < 4; in++) {
      int n0 = wn + in * 8 + t2;
      int n1 = n0 + 1;
      WNS[m0 * kWnSH + n0] = __float2half_rn(acc[im][in][0] + bnS[n0]);
      WNS[m0 * kWnSH + n1] = __float2half_rn(acc[im][in][1] + bnS[n1]);
      WNS[m1 * kWnSH + n0] = __float2half_rn(acc[im][in][2] + bnS[n0]);
      WNS[m1 * kWnSH + n1] = __float2half_rn(acc[im][in][3] + bnS[n1]);
    }
  }
  __syncthreads();

  // GEMM2: A[m=h, k=e] = v[z, h, e] (fp16, k unit stride); B from WNS.
  const __half* vz = v + (long)z * kH * kC;
  __half* const mz = m5 + (long)z * kC * kH;
  const uint32_t saB2 = smem_u32(WNS) + (uint32_t)(wn * kWnSH * 2) + b4_off_h(lane, kWnSH);

  for (int hh = 0; hh < 2; hh++) {
    const __half* Arow2 = vz + (long)(hh * 128 + row) * kC + khalf;
    load_conv16h<true, false, __half>(sAp, Arow2, 1, nullptr);
    __syncthreads();

#pragma unroll
    for (int i = 0; i < 4; i++)
#pragma unroll
      for (int j = 0; j < 4; j++)
#pragma unroll
        for (int c = 0; c < 4; c++) acc[i][j][c] = 0.f;

    for (int c = 0; c < 4; c++) {
      const uint32_t aBase = saA0 + (uint32_t)((c & 1) * kBufH * 2);
      const uint32_t bBase = saB2 + (uint32_t)(c * 64);  // c*32 halves
#pragma unroll
      for (int ks = 0; ks < 2; ks++)
        warp_mma_step_h(acc, aBase, bBase, ks, kWnSH);
      if (c + 1 < 4) {
        const int nb = (c + 1) & 1;
        load_conv16h<true, false, __half>(sAp + nb * kBufH, Arow2 + (c + 1) * 32, 1,
                                          nullptr);
      }
      __syncthreads();
    }

#pragma unroll
    for (int im = 0; im < 4; im++) {
      int m0 = hh * 128 + wm + im * 16 + g;
      int m1 = m0 + 8;
#pragma unroll
      for (int in = 0; in < 4; in++) {
        int n0 = wn + in * 8 + t2;
        int n1 = n0 + 1;
        mz[(long)n0 * kH + m0] = __float2half_rn(acc[im][in][0]);
        mz[(long)n1 * kH + m0] = __float2half_rn(acc[im][in][1]);
        mz[(long)n0 * kH + m1] = __float2half_rn(acc[im][in][2]);
        mz[(long)n1 * kH + m1] = __float2half_rn(acc[im][in][3]);
      }
    }
  }
}

// Per-(b,d,c) reciprocal of sum over w of exp(scores) stored in s (B,W,D,C).
__global__ __launch_bounds__(256) void softmax_sum(const float* __restrict__ s,
                                                   float* __restrict__ inv) {
  long t = (long)blockIdx.x * blockDim.x + threadIdx.x;  // < B*C*C
  int b = (int)(t / kCC);
  int r = (int)(t % kCC);
  const float* p = s + (long)b * kW * kCC + r;
  float l = 0.f;
#pragma unroll 8
  for (int w = 0; w < kW; w++) l += p[(long)w * kCC];
  inv[t] = 1.f / l;
}

// Transpose m5 (B,W,C,H) -> m6 (B,H,C,W), fp16.
__global__ __launch_bounds__(256) void trans_wh(const __half* __restrict__ in,
                                                __half* __restrict__ out) {
  __shared__ unsigned short tile[32][33];
  int bc = blockIdx.z;
  int b = bc / kC, c = bc % kC;
  long ibase = (long)b * kW * kC * kH + (long)c * kH;
  long obase = (long)b * kH * kC * kW + (long)c * kW;
  int w0 = blockIdx.x * 32, h0 = blockIdx.y * 32;
  int txl = threadIdx.x;
  const unsigned short* inu = reinterpret_cast<const unsigned short*>(in);
  unsigned short* outu = reinterpret_cast<unsigned short*>(out);
#pragma unroll
  for (int i = threadIdx.y; i < 32; i += 8)
    tile[i][txl] = inu[ibase + (long)(w0 + i) * (kC * kH) + h0 + txl];
  __syncthreads();
#pragma unroll
  for (int i = threadIdx.y; i < 32; i += 8)
    outu[obase + (long)(h0 + i) * (kC * kW) + w0 + txl] = tile[txl][i];
}

extern "C" void kernel_launch(void* const* d_in, const int* in_sizes, int n_in,
                              void* d_out, int out_size) {
  (void)in_sizes; (void)n_in; (void)out_size;
  const float* x  = (const float*)d_in[0];
  const float* Wq = (const float*)d_in[1];
  const float* bq = (const float*)d_in[2];
  const float* Wk = (const float*)d_in[3];
  const float* bk = (const float*)d_in[4];
  const float* Wv = (const float*)d_in[5];
  const float* bv = (const float*)d_in[6];
  const float* Wn = (const float*)d_in[7];
  const float* bn = (const float*)d_in[8];
  const float* Wo = (const float*)d_in[9];
  const float* bo = (const float*)d_in[10];
  float* out = (float*)d_out;

  __half *q, *k, *v;
  float *s, *inv;
  cudaGetSymbolAddress((void**)&q, g_q);
  cudaGetSymbolAddress((void**)&k, g_k);
  cudaGetSymbolAddress((void**)&v, g_v);
  cudaGetSymbolAddress((void**)&s, g_s);
  cudaGetSymbolAddress((void**)&inv, g_inv);

  const long HC = (long)kH * kC;
  const long CW = (long)kC * kW;
  const long CC = kCC;

  // Pass 1: fused Q/K/V projections (fp16 out). z=(b*H+h), y selects head.
  gemm_qkv<<<dim3(1, 3, kB * kH), 256>>>(x, Wq, Wk, Wv, bq, bk, bv, q, k, v);

  // Pass 2: s[b,w][c,d] = exp(sum_h q*k / sqrt(W)). z=(b*W+w). m=c, n=d, k=h.
  gemm_gen<false, false, false, true, __half, __half, float>
      <<<dim3(1, 1, kB * kW), 256>>>(
      q, 1, HC, 0, 1, kC,
      k, 1, HC, 0, 1, kC,
      s, 1, CC, 0, kC,
      nullptr, 1, nullptr, nullptr, 0.08838834764831845f, kH);

  // Pass 3: softmax denominators.
  softmax_sum<<<(int)((kB * CC) / 256), 256>>>(s, inv);

  // Pass 4+5 fused: wn in smem (fp16), m5 (B,W,C,H) fp16 into g_q.
  const int dynBytes = (2 * kBufH + kWnHalves) * 2;
  cudaFuncSetAttribute(gemm_p45, cudaFuncAttributeMaxDynamicSharedMemorySize, dynBytes);
  gemm_p45<<<dim3(1, 1, kB * kW), 256, dynBytes>>>(s, Wn, inv, v, bn, q);

  // Pass 5.5: transpose m5 (B,W,C,H) -> m6 (B,H,C,W), fp16.
  trans_wh<<<dim3(kW / 32, kH / 32, kB * kC), dim3(32, 8)>>>(q, k);

  // Pass 6: out[b,h][w,o] = sum_c m6[c,w]*Wo[c,o] + bo[o]. m=w, n=o, k=c.
  gemm_gen<false, false, false, false, __half, float, float>
      <<<dim3(1, 1, kB * kH), 256>>>(
      k, 1, CW, 0, 1, kW,
      Wo, 1, 0, 0, 1, kC,
      out, 1, CW, 0, kW,
      nullptr, 1, nullptr, bo, 1.f, kC);
}

// round 15
// speedup vs baseline: 1.8040x; 1.0042x over previous
#include <cuda_runtime.h>
#include <cuda_fp16.h>
#include <cstdint>

namespace {
constexpr int kB = 16, kH = 256, kC = 128, kW = 128;
constexpr long kCC = (long)kC * kC;
}

// Scratch (device globals: allocation-free contract).
__device__ __align__(256) __half g_q[(size_t)kB * kW * kH * kC];  // q; reused m5 (B,W,C,H)
__device__ __align__(256) __half g_k[(size_t)kB * kW * kH * kC];  // k; reused m6 (B,H,C,W)
__device__ __align__(256) __half g_v[(size_t)kB * kW * kH * kC];  // v (B,W,H,C)
__device__ __align__(256) __half g_s[(size_t)kB * kW * kC * kC];  // exp(scores) (B,W,C,D)
__device__ float g_inv[(size_t)kB * kC * kC];                     // 1/sum_w exp (B,C,D)

__device__ __forceinline__ uint32_t smem_u32(const void* p) {
  uint32_t a;
  asm("{ .reg .u64 t; cvta.to.shared.u64 t, %1; cvt.u32.u64 %0, t; }" : "=r"(a) : "l"(p));
  return a;
}

// exp on the FMA pipe; clamp +-11 so result fits fp16 (e^11 ~ 59874 < 65504).
__device__ __forceinline__ float fast_exp(float x) {
  x = fminf(fmaxf(x, -11.f), 11.f);
  float r = rintf(x * 1.44269504f);
  float f = fmaf(r, -0.6931471805599453f, x);
  float p = 1.f + f * (1.f + f * (0.5f + f * (0.16666667f +
                f * (0.041666667f + f * 0.0083333333f))));
  return p * __int_as_float(((int)r + 127) << 23);
}

// SMEM strides (halves). 40 / 136: every ldmatrix phase spans all 32 banks.
constexpr int kLdsH = 40;
constexpr int kBufH = 128 * kLdsH;      // halves per stage (5120)
constexpr int kWnSH = 136;              // wn smem row stride (halves)
constexpr int kWnHalves = 128 * kWnSH;  // 17408

__device__ __forceinline__ uint32_t h2u(__half2 h) {
  return *reinterpret_cast<uint32_t*>(&h);
}

// Load 16 k-words of one row (float). KC=true: k unit stride (float4).
template <bool KC>
__device__ __forceinline__ void ldg16(float4 r[4], const float* __restrict__ p, long sK) {
  if (KC) {
#pragma unroll
    for (int i = 0; i < 4; i++) r[i] = reinterpret_cast<const float4*>(p)[i];
  } else {
#pragma unroll
    for (int i = 0; i < 4; i++) {
      r[i].x = p[(long)(i * 4 + 0) * sK];
      r[i].y = p[(long)(i * 4 + 1) * sK];
      r[i].z = p[(long)(i * 4 + 2) * sK];
      r[i].w = p[(long)(i * 4 + 3) * sK];
    }
  }
}

// Load 16 k-elements of one row, as fp16, store 32 bytes to smem.
// T=float: convert (optionally *nrm). T=half: copy (optionally *nrm with re-round).
template <bool KC, bool NORM, typename T>
__device__ __forceinline__ void load_conv16h(__half* __restrict__ dst,
                                             const T* __restrict__ src, long sK,
                                             const float* __restrict__ nsrc) {
  uint32_t w[8];
  if constexpr (sizeof(T) == 4) {
    float4 a[4], n[4];
    ldg16<KC>(a, reinterpret_cast<const float*>(src), sK);
    if (NORM) ldg16<KC>(n, nsrc, sK);
#pragma unroll
    for (int i = 0; i < 4; i++) {
      float4 v = a[i];
      if (NORM) { v.x *= n[i].x; v.y *= n[i].y; v.z *= n[i].z; v.w *= n[i].w; }
      w[2 * i + 0] = h2u(__floats2half2_rn(v.x, v.y));
      w[2 * i + 1] = h2u(__floats2half2_rn(v.z, v.w));
    }
  } else {
    if constexpr (KC) {
      const uint4* p = reinterpret_cast<const uint4*>(src);
      uint4 u0 = p[0], u1 = p[1];
      w[0] = u0.x; w[1] = u0.y; w[2] = u0.z; w[3] = u0.w;
      w[4] = u1.x; w[5] = u1.y; w[6] = u1.z; w[7] = u1.w;
      if (NORM) {
        float4 n[4];
        ldg16<true>(n, nsrc, sK);
#pragma unroll
        for (int i = 0; i < 4; i++) {
          float2 f0 = __half22float2(*reinterpret_cast<__half2*>(&w[2 * i]));
          float2 f1 = __half22float2(*reinterpret_cast<__half2*>(&w[2 * i + 1]));
          w[2 * i + 0] = h2u(__floats2half2_rn(f0.x * n[i].x, f0.y * n[i].y));
          w[2 * i + 1] = h2u(__floats2half2_rn(f1.x * n[i].z, f1.y * n[i].w));
        }
      }
    } else {
      const unsigned short* p = reinterpret_cast<const unsigned short*>(src);
#pragma unroll
      for (int i = 0; i < 8; i++) {
        uint32_t lo = p[(long)(2 * i) * sK];
        uint32_t hi = p[(long)(2 * i + 1) * sK];
        w[i] = lo | (hi << 16);
      }
      if (NORM) {
#pragma unroll
        for (int i = 0; i < 8; i++) {
          float2 f = __half22float2(*reinterpret_cast<__half2*>(&w[i]));
          float n0 = nsrc[(long)(2 * i) * sK], n1 = nsrc[(long)(2 * i + 1) * sK];
          w[i] = h2u(__floats2half2_rn(f.x * n0, f.y * n1));
        }
      }
    }
  }
  const uint32_t d = smem_u32(dst);
  asm volatile("st.shared.v4.b32 [%0], {%1,%2,%3,%4};"
               :: "r"(d), "r"(w[0]), "r"(w[1]), "r"(w[2]), "r"(w[3]));
  asm volatile("st.shared.v4.b32 [%0], {%1,%2,%3,%4};"
               :: "r"(d + 16), "r"(w[4]), "r"(w[5]), "r"(w[6]), "r"(w[7]));
}

template <typename TC>
__device__ __forceinline__ void stC(TC* p, float v) {
  if constexpr (sizeof(TC) == 4) *reinterpret_cast<float*>(p) = v;
  else *reinterpret_cast<__half*>(p) = __float2half_rn(v);
}

__device__ __forceinline__ void ldsm_x4(uint32_t r[4], uint32_t addr) {
  asm volatile("ldmatrix.sync.aligned.m8n8.x4.shared.b16 {%0,%1,%2,%3}, [%4];"
               : "=r"(r[0]), "=r"(r[1]), "=r"(r[2]), "=r"(r[3]) : "r"(addr));
}

// Per-lane byte offsets for ldmatrix.x4 (SH = row stride in halves).
__device__ __forceinline__ uint32_t a4_off_h(int lane, int SH) {
  return (uint32_t)((((lane & 7) + ((lane >> 3) & 1) * 8) * SH * 2) + (lane >> 4) * 16);
}
__device__ __forceinline__ uint32_t b4_off_h(int lane, int SH) {
  return (uint32_t)((((lane & 7) + ((lane >> 4) & 1) * 8) * SH * 2) +
                    ((lane >> 3) & 1) * 16);
}

__device__ __forceinline__ void mma_f16(float acc[4], const uint32_t a[4],
                                        const uint32_t b[2]) {
  asm volatile(
      "mma.sync.aligned.m16n8k16.row.col.f32.f16.f16.f32 "
      "{%0,%1,%2,%3}, {%4,%5,%6,%7}, {%8,%9}, {%0,%1,%2,%3};"
      : "+f"(acc[0]), "+f"(acc[1]), "+f"(acc[2]), "+f"(acc[3])
      : "r"(a[0]), "r"(a[1]), "r"(a[2]), "r"(a[3]), "r"(b[0]), "r"(b[1]));
}

// One K=16 step of the 64x32 warp tile: 4 A ldsm.x4, 2 B ldsm.x4, 16 MMAs.
__device__ __forceinline__ void warp_mma_step_h(float acc[4][4][4], uint32_t aBase,
                                                uint32_t bBase, int ks, int strideBh) {
  uint32_t af[4][4], bt0[4], bt1[4];
#pragma unroll
  for (int im = 0; im < 4; im++)
    ldsm_x4(af[im], aBase + (uint32_t)(im * 16 * kLdsH * 2 + ks * 32));
  ldsm_x4(bt0, bBase + (uint32_t)(ks * 32));
  ldsm_x4(bt1, bBase + (uint32_t)(16 * strideBh * 2 + ks * 32));
  uint32_t bf[4][2] = {{bt0[0], bt0[1]}, {bt0[2], bt0[3]},
                       {bt1[0], bt1[1]}, {bt1[2], bt1[3]}};
#pragma unroll
  for (int im = 0; im < 4; im++)
#pragma unroll
    for (int in = 0; in < 4; in++) mma_f16(acc[im][in], af[im], bf[in]);
}

// Core 128x128 GEMM body via mma.sync fp16 (fp32 accumulate).
template <bool AKC, bool BKC, bool NORM, bool EEPI, typename TA, typename TB, typename TC>
__device__ __forceinline__ void gemm_body(
    const TA* __restrict__ A, long sAm, long sAk,
    const TB* __restrict__ Bp, long sBn, long sBk,
    TC* __restrict__ Cp, long sCn,
    const float* __restrict__ nrm,
    const float* __restrict__ bias_m, const float* __restrict__ bias_n,
    float alpha, int K) {
  __shared__ __half As[2 * kBufH];
  __shared__ __half Bs[2 * kBufH];
  __shared__ float bmS[128], bnS[128];

  const int tid = threadIdx.x;
  const int lane = tid & 31, wid = tid >> 5;
  const int wm = (wid & 1) * 64, wn = (wid >> 1) * 32;
  const int row = tid >> 1, khalf = (tid & 1) * 16;

  if (!EEPI && tid < 128) {
    bmS[tid] = bias_m ? bias_m[tid] : 0.f;
    bnS[tid] = bias_n ? bias_n[tid] : 0.f;
  }

  const TA* Arow = A + (long)row * sAm + (long)khalf * sAk;
  const TB* Brow = Bp + (long)row * sBn + (long)khalf * sBk;
  const float* Nrow = NORM ? nrm + (long)row * sAm + (long)khalf * sAk : nullptr;
  __half* const sA = As + row * kLdsH + khalf;
  __half* const sB = Bs + row * kLdsH + khalf;

  const uint32_t saA0 = smem_u32(As) + (uint32_t)(wm * kLdsH * 2) + a4_off_h(lane, kLdsH);
  const uint32_t saB0 = smem_u32(Bs) + (uint32_t)(wn * kLdsH * 2) + b4_off_h(lane, kLdsH);

  load_conv16h<AKC, NORM, TA>(sA, Arow, sAk, Nrow);
  load_conv16h<BKC, false, TB>(sB, Brow, sBk, nullptr);
  __syncthreads();

  float acc[4][4][4];
#pragma unroll
  for (int i = 0; i < 4; i++)
#pragma unroll
    for (int j = 0; j < 4; j++)
#pragma unroll
      for (int c = 0; c < 4; c++) acc[i][j][c] = 0.f;

  const int nch = K >> 5;
  for (int c = 0; c < nch; c++) {
    const uint32_t stg = (uint32_t)((c & 1) * kBufH * 2);
#pragma unroll
    for (int ks = 0; ks < 2; ks++)
      warp_mma_step_h(acc, saA0 + stg, saB0 + stg, ks, kLdsH);
    if (c + 1 < nch) {
      const int nb = (c + 1) & 1;
      const long ko = (long)(c + 1) * 32;
      load_conv16h<AKC, NORM, TA>(sA + nb * kBufH, Arow + ko * sAk, sAk,
                                  NORM ? Nrow + ko * sAk : nullptr);
      load_conv16h<BKC, false, TB>(sB + nb * kBufH, Brow + ko * sBk, sBk, nullptr);
    }
    __syncthreads();
  }

  const int g = lane >> 2, t2 = (lane & 3) * 2;
#pragma unroll
  for (int im = 0; im < 4; im++) {
    int m0 = wm + im * 16 + g;
    int m1 = m0 + 8;
    float bm0 = EEPI ? 0.f : bmS[m0], bm1 = EEPI ? 0.f : bmS[m1];
#pragma unroll
    for (int in = 0; in < 4; in++) {
      int n0 = wn + in * 8 + t2;
      int n1 = n0 + 1;
      if (EEPI) {
        stC(Cp + (long)n0 * sCn + m0, fast_exp(alpha * acc[im][in][0]));
        stC(Cp + (long)n1 * sCn + m0, fast_exp(alpha * acc[im][in][1]));
        stC(Cp + (long)n0 * sCn + m1, fast_exp(alpha * acc[im][in][2]));
        stC(Cp + (long)n1 * sCn + m1, fast_exp(alpha * acc[im][in][3]));
      } else {
        float bn0 = bnS[n0], bn1 = bnS[n1];
        stC(Cp + (long)n0 * sCn + m0, alpha * acc[im][in][0] + bm0 + bn0);
        stC(Cp + (long)n1 * sCn + m0, alpha * acc[im][in][1] + bm0 + bn1);
        stC(Cp + (long)n0 * sCn + m1, alpha * acc[im][in][2] + bm1 + bn0);
        stC(Cp + (long)n1 * sCn + m1, alpha * acc[im][in][3] + bm1 + bn1);
      }
    }
  }
}

// Fused QKV: grid (1, 3, B*H); y selects weight/bias/output; fp16 outputs.
__global__ __launch_bounds__(256, 2) void gemm_qkv(
    const float* __restrict__ x,
    const float* __restrict__ Wq, const float* __restrict__ Wk, const float* __restrict__ Wv,
    const float* __restrict__ bq, const float* __restrict__ bk, const float* __restrict__ bv,
    __half* __restrict__ q, __half* __restrict__ k, __half* __restrict__ v) {
  const int z = blockIdx.z, y = blockIdx.y;
  const float* A = (y == 0) ? Wq : (y == 1) ? Wk : Wv;
  const float* bm = (y == 0) ? bq : (y == 1) ? bk : bv;
  __half* C = ((y == 0) ? q : (y == 1) ? k : v) +
              (long)(z / kH) * ((long)kW * kH * kC) + (long)(z % kH) * kC;
  const float* B = x + (long)z * kC * kW;
  gemm_body<false, false, false, false, float, float, __half>(
      A, 1, kC, B, 1, kW, C, (long)kH * kC, nullptr, bm, nullptr, 1.f, kC);
}

template <bool AKC, bool BKC, bool NORM, bool EEPI, typename TA, typename TB, typename TC>
__global__ __launch_bounds__(256, 2) void gemm_gen(
    const TA* __restrict__ A, int a_div, long a_so, long a_si, long sAm, long sAk,
    const TB* __restrict__ Bp, int b_div, long b_so, long b_si, long sBn, long sBk,
    TC* __restrict__ Cp, int c_div, long c_so, long c_si, long sCn,
    const float* __restrict__ nrm_base, int nrm_div,
    const float* __restrict__ bias_m, const float* __restrict__ bias_n,
    float alpha, int K) {
  const int z = blockIdx.z, bx = blockIdx.x, by = blockIdx.y;
  A += (long)(z / a_div) * a_so + (long)(z % a_div) * a_si + (long)bx * 128 * sAm;
  Bp += (long)(z / b_div) * b_so + (long)(z % b_div) * b_si + (long)by * 128 * sBn;
  Cp += (long)(z / c_div) * c_so + (long)(z % c_div) * c_si + (long)bx * 128 +
        (long)by * 128 * sCn;
  const float* nrm = nullptr;
  if (NORM) nrm = nrm_base + (long)(z / nrm_div) * kCC + (long)bx * 128 * sAm;
  gemm_body<AKC, BKC, NORM, EEPI, TA, TB, TC>(
      A, sAm, sAk, Bp, sBn, sBk, Cp, sCn, nrm,
      bias_m ? bias_m + bx * 128 : nullptr,
      bias_n ? bias_n + by * 128 : nullptr, alpha, K);
}

// Fused pass4+pass5 per z=(b,w). GEMM1: A = s (fp16, d unit stride) * inv,
// B = Wn (fp32 strided) -> wn in smem (fp16). GEMM2: A = v (fp16, unit), B = wn.
__global__ __launch_bounds__(256, 2) void gemm_p45(
    const __half* __restrict__ s, const float* __restrict__ Wn,
    const float* __restrict__ inv, const __half* __restrict__ v,
    const float* __restrict__ bn, __half* __restrict__ m5) {
  extern __shared__ __half dynH[];
  __half* const SA = dynH;
  __half* const SB = dynH + 2 * kBufH;
  __half* const WNS = dynH + 2 * kBufH;  // alias of SB region (+ extension)
  __shared__ float bnS[128];

  const int tid = threadIdx.x;
  const int lane = tid & 31, wid = tid >> 5;
  const int wm = (wid & 1) * 64, wn = (wid >> 1) * 32;
  const int row = tid >> 1, khalf = (tid & 1) * 16;
  const int z = blockIdx.z;
  const int b = z >> 7;  // z = b*kW + w

  if (tid < 128) bnS[tid] = bn[tid];

  // s layout (B,W,C,D): A[m=c stride kC, k=d unit]; inv (B,C,D) matches.
  const __half* Arow1 = s + (long)z * kCC + (long)row * kC + khalf;
  const float* Nrow1 = inv + (long)b * kCC + (long)row * kC + khalf;
  const float* Brow1 = Wn + row + (long)khalf * kC;
  __half* const sAp = SA + row * kLdsH + khalf;
  __half* const sBp = SB + row * kLdsH + khalf;

  const uint32_t saA0 = smem_u32(SA) + (uint32_t)(wm * kLdsH * 2) + a4_off_h(lane, kLdsH);
  const uint32_t saB0 = smem_u32(SB) + (uint32_t)(wn * kLdsH * 2) + b4_off_h(lane, kLdsH);

  load_conv16h<true, true, __half>(sAp, Arow1, 1, Nrow1);
  load_conv16h<false, false, float>(sBp, Brow1, kC, nullptr);
  __syncthreads();

  float acc[4][4][4];
#pragma unroll
  for (int i = 0; i < 4; i++)
#pragma unroll
    for (int j = 0; j < 4; j++)
#pragma unroll
      for (int c = 0; c < 4; c++) acc[i][j][c] = 0.f;

  for (int c = 0; c < 4; c++) {
    const uint32_t stg = (uint32_t)((c & 1) * kBufH * 2);
#pragma unroll
    for (int ks = 0; ks < 2; ks++)
      warp_mma_step_h(acc, saA0 + stg, saB0 + stg, ks, kLdsH);
    if (c + 1 < 4) {
      const int nb = (c + 1) & 1;
      const long ko = (long)(c + 1) * 32;
      load_conv16h<true, true, __half>(sAp + nb * kBufH, Arow1 + ko, 1, Nrow1 + ko);
      load_conv16h<false, false, float>(sBp + nb * kBufH, Brow1 + ko * kC, kC, nullptr);
    }
    __syncthreads();
  }

  // Epilogue1: wn tile -> WNS[c*kWnSH + e] (fp16), +bn[e].
  const int g = lane >> 2, t2 = (lane & 3) * 2;
#pragma unroll
  for (int im = 0; im < 4; im++) {
    int m0 = wm + im * 16 + g;
    int m1 = m0 + 8;
#pragma unroll
    for (int in = 0; in < 4; in++) {
      int n0 = wn + in * 8 + t2;
      int n1 = n0 + 1;
      WNS[m0 * kWnSH + n0] = __float2half_rn(acc[im][in][0] + bnS[n0]);
      WNS[m0 * kWnSH + n1] = __float2half_rn(acc[im][in][1] + bnS[n1]);
      WNS[m1 * kWnSH + n0] = __float2half_rn(acc[im][in][2] + bnS[n0]);
      WNS[m1 * kWnSH + n1] = __float2half_rn(acc[im][in][3] + bnS[n1]);
    }
  }
  __syncthreads();

  // GEMM2: A[m=h, k=e] = v[z, h, e] (fp16, k unit stride); B from WNS.
  const __half* vz = v + (long)z * kH * kC;
  __half* const mz = m5 + (long)z * kC * kH;
  const uint32_t saB2 = smem_u32(WNS) + (uint32_t)(wn * kWnSH * 2) + b4_off_h(lane, kWnSH);

  for (int hh = 0; hh < 2; hh++) {
    const __half* Arow2 = vz + (long)(hh * 128 + row) * kC + khalf;
    load_conv16h<true, false, __half>(sAp, Arow2, 1, nullptr);
    __syncthreads();

#pragma unroll
    for (int i = 0; i < 4; i++)
#pragma unroll
      for (int j = 0; j < 4; j++)
#pragma unroll
        for (int c = 0; c < 4; c++) acc[i][j][c] = 0.f;

    for (int c = 0; c < 4; c++) {
      const uint32_t aBase = saA0 + (uint32_t)((c & 1) * kBufH * 2);
      const uint32_t bBase = saB2 + (uint32_t)(c * 64);  // c*32 halves
#pragma unroll
      for (int ks = 0; ks < 2; ks++)
        warp_mma_step_h(acc, aBase, bBase, ks, kWnSH);
      if (c + 1 < 4) {
        const int nb = (c + 1) & 1;
        load_conv16h<true, false, __half>(sAp + nb * kBufH, Arow2 + (c + 1) * 32, 1,
                                          nullptr);
      }
      __syncthreads();
    }

#pragma unroll
    for (int im = 0; im < 4; im++) {
      int m0 = hh * 128 + wm + im * 16 + g;
      int m1 = m0 + 8;
#pragma unroll
      for (int in = 0; in < 4; in++) {
        int n0 = wn + in * 8 + t2;
        int n1 = n0 + 1;
        mz[(long)n0 * kH + m0] = __float2half_rn(acc[im][in][0]);
        mz[(long)n1 * kH + m0] = __float2half_rn(acc[im][in][1]);
        mz[(long)n0 * kH + m1] = __float2half_rn(acc[im][in][2]);
        mz[(long)n1 * kH + m1] = __float2half_rn(acc[im][in][3]);
      }
    }
  }
}

// Per-(b,c,d) reciprocal of sum over w of exp(scores) stored in s (B,W,C,D).
__global__ __launch_bounds__(256) void softmax_sum(const __half* __restrict__ s,
                                                   float* __restrict__ inv) {
  long t = (long)blockIdx.x * blockDim.x + threadIdx.x;  // < B*C*C
  int b = (int)(t / kCC);
  int r = (int)(t % kCC);
  const __half* p = s + (long)b * kW * kCC + r;
  float l = 0.f;
#pragma unroll 8
  for (int w = 0; w < kW; w++) l += __half2float(p[(long)w * kCC]);
  inv[t] = 1.f / l;
}

// Transpose m5 (B,W,C,H) -> m6 (B,H,C,W), fp16. Pad 34 => conflict-free 2B.
__global__ __launch_bounds__(256) void trans_wh(const __half* __restrict__ in,
                                                __half* __restrict__ out) {
  __shared__ unsigned short tile[32][34];
  int bc = blockIdx.z;
  int b = bc / kC, c = bc % kC;
  long ibase = (long)b * kW * kC * kH + (long)c * kH;
  long obase = (long)b * kH * kC * kW + (long)c * kW;
  int w0 = blockIdx.x * 32, h0 = blockIdx.y * 32;
  int txl = threadIdx.x;
  const unsigned short* inu = reinterpret_cast<const unsigned short*>(in);
  unsigned short* outu = reinterpret_cast<unsigned short*>(out);
#pragma unroll
  for (int i = threadIdx.y; i < 32; i += 8)
    tile[i][txl] = inu[ibase + (long)(w0 + i) * (kC * kH) + h0 + txl];
  __syncthreads();
#pragma unroll
  for (int i = threadIdx.y; i < 32; i += 8)
    outu[obase + (long)(h0 + i) * (kC * kW) + w0 + txl] = tile[txl][i];
}

extern "C" void kernel_launch(void* const* d_in, const int* in_sizes, int n_in,
                              void* d_out, int out_size) {
  (void)in_sizes; (void)n_in; (void)out_size;
  const float* x  = (const float*)d_in[0];
  const float* Wq = (const float*)d_in[1];
  const float* bq = (const float*)d_in[2];
  const float* Wk = (const float*)d_in[3];
  const float* bk = (const float*)d_in[4];
  const float* Wv = (const float*)d_in[5];
  const float* bv = (const float*)d_in[6];
  const float* Wn = (const float*)d_in[7];
  const float* bn = (const float*)d_in[8];
  const float* Wo = (const float*)d_in[9];
  const float* bo = (const float*)d_in[10];
  float* out = (float*)d_out;

  __half *q, *k, *v, *s;
  float *inv;
  cudaGetSymbolAddress((void**)&q, g_q);
  cudaGetSymbolAddress((void**)&k, g_k);
  cudaGetSymbolAddress((void**)&v, g_v);
  cudaGetSymbolAddress((void**)&s, g_s);
  cudaGetSymbolAddress((void**)&inv, g_inv);

  const long HC = (long)kH * kC;
  const long CW = (long)kC * kW;
  const long CC = kCC;

  // Pass 1: fused Q/K/V projections (fp16 out). z=(b*H+h), y selects head.
  gemm_qkv<<<dim3(1, 3, kB * kH), 256>>>(x, Wq, Wk, Wv, bq, bk, bv, q, k, v);

  // Pass 2: s[b,w,c,d] = exp(sum_h k[h,d] q[h,c] / sqrt(W)). m=d, n=c, k=h.
  gemm_gen<false, false, false, true, __half, __half, __half>
      <<<dim3(1, 1, kB * kW), 256>>>(
      k, 1, HC, 0, 1, kC,
      q, 1, HC, 0, 1, kC,
      s, 1, CC, 0, kC,
      nullptr, 1, nullptr, nullptr, 0.08838834764831845f, kH);

  // Pass 3: softmax denominators (inv in (B,C,D)).
  softmax_sum<<<(int)((kB * CC) / 256), 256>>>(s, inv);

  // Pass 4+5 fused: wn in smem (fp16), m5 (B,W,C,H) fp16 into g_q.
  const int dynBytes = (2 * kBufH + kWnHalves) * 2;
  cudaFuncSetAttribute(gemm_p45, cudaFuncAttributeMaxDynamicSharedMemorySize, dynBytes);
  gemm_p45<<<dim3(1, 1, kB * kW), 256, dynBytes>>>(s, Wn, inv, v, bn, q);

  // Pass 5.5: transpose m5 (B,W,C,H) -> m6 (B,H,C,W), fp16.
  trans_wh<<<dim3(kW / 32, kH / 32, kB * kC), dim3(32, 8)>>>(q, k);

  // Pass 6: out[b,h][w,o] = sum_c m6[c,w]*Wo[c,o] + bo[o]. m=w, n=o, k=c.
  gemm_gen<false, false, false, false, __half, float, float>
      <<<dim3(1, 1, kB * kH), 256>>>(
      k, 1, CW, 0, 1, kW,
      Wo, 1, 0, 0, 1, kC,
      out, 1, CW, 0, kW,
      nullptr, 1, nullptr, bo, 1.f, kC);
}

// round 16
// speedup vs baseline: 1.9187x; 1.0636x over previous
#include <cuda_runtime.h>
#include <cuda_fp16.h>
#include <cstdint>

namespace {
constexpr int kB = 16, kH = 256, kC = 128, kW = 128;
constexpr long kCC = (long)kC * kC;
}

// Scratch (device globals: allocation-free contract).
__device__ __align__(256) __half g_q[(size_t)kB * kW * kH * kC];  // q; reused m5 (B,W,C,H)
__device__ __align__(256) __half g_k[(size_t)kB * kW * kH * kC];  // k; reused m6 (B,H,C,W)
__device__ __align__(256) __half g_v[(size_t)kB * kW * kH * kC];  // v (B,W,H,C)
__device__ __align__(256) __half g_s[(size_t)kB * kW * kC * kC];  // exp(scores) (B,W,C,D)
__device__ float g_inv[(size_t)kB * kC * kC];                     // 1/sum_w exp (B,C,D)
// fp16 transposed weights: [0..2]=Wq/Wk/WvT [d][c], [3]=WnT [e][d], [4]=WoT [o][c].
__device__ __align__(256) __half g_wT[5 * 128 * 128];

__device__ __forceinline__ uint32_t smem_u32(const void* p) {
  uint32_t a;
  asm("{ .reg .u64 t; cvta.to.shared.u64 t, %1; cvt.u32.u64 %0, t; }" : "=r"(a) : "l"(p));
  return a;
}

// exp on the FMA pipe; clamp +-11 so result fits fp16 (e^11 ~ 59874 < 65504).
__device__ __forceinline__ float fast_exp(float x) {
  x = fminf(fmaxf(x, -11.f), 11.f);
  float r = rintf(x * 1.44269504f);
  float f = fmaf(r, -0.6931471805599453f, x);
  float p = 1.f + f * (1.f + f * (0.5f + f * (0.16666667f +
                f * (0.041666667f + f * 0.0083333333f))));
  return p * __int_as_float(((int)r + 127) << 23);
}

// SMEM strides (halves). 40 / 136: every ldmatrix phase spans all 32 banks.
constexpr int kLdsH = 40;
constexpr int kBufH = 128 * kLdsH;      // halves per stage (5120)
constexpr int kWnSH = 136;              // resident-tile smem row stride (halves)
constexpr int kWnHalves = 128 * kWnSH;  // 17408

__device__ __forceinline__ uint32_t h2u(__half2 h) {
  return *reinterpret_cast<uint32_t*>(&h);
}

// Load 16 k-words of one row (float). KC=true: k unit stride (float4).
template <bool KC>
__device__ __forceinline__ void ldg16(float4 r[4], const float* __restrict__ p, long sK) {
  if (KC) {
#pragma unroll
    for (int i = 0; i < 4; i++) r[i] = reinterpret_cast<const float4*>(p)[i];
  } else {
#pragma unroll
    for (int i = 0; i < 4; i++) {
      r[i].x = p[(long)(i * 4 + 0) * sK];
      r[i].y = p[(long)(i * 4 + 1) * sK];
      r[i].z = p[(long)(i * 4 + 2) * sK];
      r[i].w = p[(long)(i * 4 + 3) * sK];
    }
  }
}

// Load 16 k-elements of one row, as fp16, store 32 bytes to smem.
template <bool KC, bool NORM, typename T>
__device__ __forceinline__ void load_conv16h(__half* __restrict__ dst,
                                             const T* __restrict__ src, long sK,
                                             const float* __restrict__ nsrc) {
  uint32_t w[8];
  if constexpr (sizeof(T) == 4) {
    float4 a[4], n[4];
    ldg16<KC>(a, reinterpret_cast<const float*>(src), sK);
    if (NORM) ldg16<KC>(n, nsrc, sK);
#pragma unroll
    for (int i = 0; i < 4; i++) {
      float4 v = a[i];
      if (NORM) { v.x *= n[i].x; v.y *= n[i].y; v.z *= n[i].z; v.w *= n[i].w; }
      w[2 * i + 0] = h2u(__floats2half2_rn(v.x, v.y));
      w[2 * i + 1] = h2u(__floats2half2_rn(v.z, v.w));
    }
  } else {
    if constexpr (KC) {
      const uint4* p = reinterpret_cast<const uint4*>(src);
      uint4 u0 = p[0], u1 = p[1];
      w[0] = u0.x; w[1] = u0.y; w[2] = u0.z; w[3] = u0.w;
      w[4] = u1.x; w[5] = u1.y; w[6] = u1.z; w[7] = u1.w;
      if (NORM) {
        float4 n[4];
        ldg16<true>(n, nsrc, sK);
#pragma unroll
        for (int i = 0; i < 4; i++) {
          float2 f0 = __half22float2(*reinterpret_cast<__half2*>(&w[2 * i]));
          float2 f1 = __half22float2(*reinterpret_cast<__half2*>(&w[2 * i + 1]));
          w[2 * i + 0] = h2u(__floats2half2_rn(f0.x * n[i].x, f0.y * n[i].y));
          w[2 * i + 1] = h2u(__floats2half2_rn(f1.x * n[i].z, f1.y * n[i].w));
        }
      }
    } else {
      const unsigned short* p = reinterpret_cast<const unsigned short*>(src);
#pragma unroll
      for (int i = 0; i < 8; i++) {
        uint32_t lo = p[(long)(2 * i) * sK];
        uint32_t hi = p[(long)(2 * i + 1) * sK];
        w[i] = lo | (hi << 16);
      }
      if (NORM) {
#pragma unroll
        for (int i = 0; i < 8; i++) {
          float2 f = __half22float2(*reinterpret_cast<__half2*>(&w[i]));
          float n0 = nsrc[(long)(2 * i) * sK], n1 = nsrc[(long)(2 * i + 1) * sK];
          w[i] = h2u(__floats2half2_rn(f.x * n0, f.y * n1));
        }
      }
    }
  }
  const uint32_t d = smem_u32(dst);
  asm volatile("st.shared.v4.b32 [%0], {%1,%2,%3,%4};"
               :: "r"(d), "r"(w[0]), "r"(w[1]), "r"(w[2]), "r"(w[3]));
  asm volatile("st.shared.v4.b32 [%0], {%1,%2,%3,%4};"
               :: "r"(d + 16), "r"(w[4]), "r"(w[5]), "r"(w[6]), "r"(w[7]));
}

template <typename TC>
__device__ __forceinline__ void stC(TC* p, float v) {
  if constexpr (sizeof(TC) == 4) *reinterpret_cast<float*>(p) = v;
  else *reinterpret_cast<__half*>(p) = __float2half_rn(v);
}

__device__ __forceinline__ void ldsm_x4(uint32_t r[4], uint32_t addr) {
  asm volatile("ldmatrix.sync.aligned.m8n8.x4.shared.b16 {%0,%1,%2,%3}, [%4];"
               : "=r"(r[0]), "=r"(r[1]), "=r"(r[2]), "=r"(r[3]) : "r"(addr));
}

// Per-lane byte offsets for ldmatrix.x4 (SH = row stride in halves).
__device__ __forceinline__ uint32_t a4_off_h(int lane, int SH) {
  return (uint32_t)((((lane & 7) + ((lane >> 3) & 1) * 8) * SH * 2) + (lane >> 4) * 16);
}
__device__ __forceinline__ uint32_t b4_off_h(int lane, int SH) {
  return (uint32_t)((((lane & 7) + ((lane >> 4) & 1) * 8) * SH * 2) +
                    ((lane >> 3) & 1) * 16);
}

__device__ __forceinline__ void mma_f16(float acc[4], const uint32_t a[4],
                                        const uint32_t b[2]) {
  asm volatile(
      "mma.sync.aligned.m16n8k16.row.col.f32.f16.f16.f32 "
      "{%0,%1,%2,%3}, {%4,%5,%6,%7}, {%8,%9}, {%0,%1,%2,%3};"
      : "+f"(acc[0]), "+f"(acc[1]), "+f"(acc[2]), "+f"(acc[3])
      : "r"(a[0]), "r"(a[1]), "r"(a[2]), "r"(a[3]), "r"(b[0]), "r"(b[1]));
}

// One K=16 step of the 64x32 warp tile: 4 A ldsm.x4, 2 B ldsm.x4, 16 MMAs.
__device__ __forceinline__ void warp_mma_step_h(float acc[4][4][4], uint32_t aBase,
                                                uint32_t bBase, int ks, int strideBh) {
  uint32_t af[4][4], bt0[4], bt1[4];
#pragma unroll
  for (int im = 0; im < 4; im++)
    ldsm_x4(af[im], aBase + (uint32_t)(im * 16 * kLdsH * 2 + ks * 32));
  ldsm_x4(bt0, bBase + (uint32_t)(ks * 32));
  ldsm_x4(bt1, bBase + (uint32_t)(16 * strideBh * 2 + ks * 32));
  uint32_t bf[4][2] = {{bt0[0], bt0[1]}, {bt0[2], bt0[3]},
                       {bt1[0], bt1[1]}, {bt1[2], bt1[3]}};
#pragma unroll
  for (int im = 0; im < 4; im++)
#pragma unroll
    for (int in = 0; in < 4; in++) mma_f16(acc[im][in], af[im], bf[in]);
}

// Weight prep: g_wT[m] = transpose(W_m) in fp16. m 0..4.
__global__ __launch_bounds__(256) void prep_w(
    const float* __restrict__ Wq, const float* __restrict__ Wk,
    const float* __restrict__ Wv, const float* __restrict__ Wn,
    const float* __restrict__ Wo) {
  int t = blockIdx.x * 256 + threadIdx.x;  // 0..16383
  int m = blockIdx.y;
  const float* src = (m == 0) ? Wq : (m == 1) ? Wk : (m == 2) ? Wv : (m == 3) ? Wn : Wo;
  int r = t >> 7, c = t & 127;
  g_wT[m * 16384 + t] = __float2half_rn(src[c * 128 + r]);
}

// Core 128x128 GEMM body via mma.sync fp16 (fp32 accumulate).
template <bool AKC, bool BKC, bool NORM, bool EEPI, typename TA, typename TB, typename TC>
__device__ __forceinline__ void gemm_body(
    const TA* __restrict__ A, long sAm, long sAk,
    const TB* __restrict__ Bp, long sBn, long sBk,
    TC* __restrict__ Cp, long sCn,
    const float* __restrict__ nrm,
    const float* __restrict__ bias_m, const float* __restrict__ bias_n,
    float alpha, int K) {
  __shared__ __half As[2 * kBufH];
  __shared__ __half Bs[2 * kBufH];
  __shared__ float bmS[128], bnS[128];

  const int tid = threadIdx.x;
  const int lane = tid & 31, wid = tid >> 5;
  const int wm = (wid & 1) * 64, wn = (wid >> 1) * 32;
  const int row = tid >> 1, khalf = (tid & 1) * 16;

  if (!EEPI && tid < 128) {
    bmS[tid] = bias_m ? bias_m[tid] : 0.f;
    bnS[tid] = bias_n ? bias_n[tid] : 0.f;
  }

  const TA* Arow = A + (long)row * sAm + (long)khalf * sAk;
  const TB* Brow = Bp + (long)row * sBn + (long)khalf * sBk;
  const float* Nrow = NORM ? nrm + (long)row * sAm + (long)khalf * sAk : nullptr;
  __half* const sA = As + row * kLdsH + khalf;
  __half* const sB = Bs + row * kLdsH + khalf;

  const uint32_t saA0 = smem_u32(As) + (uint32_t)(wm * kLdsH * 2) + a4_off_h(lane, kLdsH);
  const uint32_t saB0 = smem_u32(Bs) + (uint32_t)(wn * kLdsH * 2) + b4_off_h(lane, kLdsH);

  load_conv16h<AKC, NORM, TA>(sA, Arow, sAk, Nrow);
  load_conv16h<BKC, false, TB>(sB, Brow, sBk, nullptr);
  __syncthreads();

  float acc[4][4][4];
#pragma unroll
  for (int i = 0; i < 4; i++)
#pragma unroll
    for (int j = 0; j < 4; j++)
#pragma unroll
      for (int c = 0; c < 4; c++) acc[i][j][c] = 0.f;

  const int nch = K >> 5;
  for (int c = 0; c < nch; c++) {
    const uint32_t stg = (uint32_t)((c & 1) * kBufH * 2);
#pragma unroll
    for (int ks = 0; ks < 2; ks++)
      warp_mma_step_h(acc, saA0 + stg, saB0 + stg, ks, kLdsH);
    if (c + 1 < nch) {
      const int nb = (c + 1) & 1;
      const long ko = (long)(c + 1) * 32;
      load_conv16h<AKC, NORM, TA>(sA + nb * kBufH, Arow + ko * sAk, sAk,
                                  NORM ? Nrow + ko * sAk : nullptr);
      load_conv16h<BKC, false, TB>(sB + nb * kBufH, Brow + ko * sBk, sBk, nullptr);
    }
    __syncthreads();
  }

  const int g = lane >> 2, t2 = (lane & 3) * 2;
#pragma unroll
  for (int im = 0; im < 4; im++) {
    int m0 = wm + im * 16 + g;
    int m1 = m0 + 8;
    float bm0 = EEPI ? 0.f : bmS[m0], bm1 = EEPI ? 0.f : bmS[m1];
#pragma unroll
    for (int in = 0; in < 4; in++) {
      int n0 = wn + in * 8 + t2;
      int n1 = n0 + 1;
      if (EEPI) {
        stC(Cp + (long)n0 * sCn + m0, fast_exp(alpha * acc[im][in][0]));
        stC(Cp + (long)n1 * sCn + m0, fast_exp(alpha * acc[im][in][1]));
        stC(Cp + (long)n0 * sCn + m1, fast_exp(alpha * acc[im][in][2]));
        stC(Cp + (long)n1 * sCn + m1, fast_exp(alpha * acc[im][in][3]));
      } else {
        float bn0 = bnS[n0], bn1 = bnS[n1];
        stC(Cp + (long)n0 * sCn + m0, alpha * acc[im][in][0] + bm0 + bn0);
        stC(Cp + (long)n1 * sCn + m0, alpha * acc[im][in][1] + bm0 + bn1);
        stC(Cp + (long)n0 * sCn + m1, alpha * acc[im][in][2] + bm1 + bn0);
        stC(Cp + (long)n1 * sCn + m1, alpha * acc[im][in][3] + bm1 + bn1);
      }
    }
  }
}

// QKV, one block per z=(b*H+h): x tile -> fp16 smem ONCE, then 3 sequential
// GEMMs (A = fp16 transposed weights, vector loads) against the resident B.
__global__ __launch_bounds__(256, 2) void gemm_qkv3(
    const float* __restrict__ x, const __half* __restrict__ wT,
    const float* __restrict__ bq, const float* __restrict__ bk,
    const float* __restrict__ bv,
    __half* __restrict__ q, __half* __restrict__ k, __half* __restrict__ v) {
  extern __shared__ __half dynH[];
  __half* const Bfull = dynH;             // 128 rows(w) x kWnSH (k=c)
  __half* const Ast = dynH + kWnHalves;   // 2 stages x 128 x kLdsH
  __shared__ float biasS[3][128];

  const int tid = threadIdx.x;
  const int lane = tid & 31, wid = tid >> 5;
  const int wm = (wid & 1) * 64, wn = (wid >> 1) * 32;
  const int row = tid >> 1, khalf = (tid & 1) * 16;
  const int z = blockIdx.z;

  if (tid < 128) {
    biasS[0][tid] = bq[tid];
    biasS[1][tid] = bk[tid];
    biasS[2][tid] = bv[tid];
  }

  // Fill B once: x[z] is [c][w]; B[n=w(row), k=c] -> strided fp32.
  const float* xz = x + (long)z * kC * kW;
#pragma unroll
  for (int c4 = 0; c4 < 4; c4++)
    load_conv16h<false, false, float>(Bfull + row * kWnSH + c4 * 32 + khalf,
                                      xz + row + (long)(c4 * 32 + khalf) * kW, kW,
                                      nullptr);
  __syncthreads();

  const uint32_t saB0 = smem_u32(Bfull) + (uint32_t)(wn * kWnSH * 2) + b4_off_h(lane, kWnSH);
  const uint32_t saA0 = smem_u32(Ast) + (uint32_t)(wm * kLdsH * 2) + a4_off_h(lane, kLdsH);
  __half* const sAp = Ast + row * kLdsH + khalf;

  const long zoff = (long)(z / kH) * ((long)kW * kH * kC) + (long)(z % kH) * kC;
  const int g = lane >> 2, t2 = (lane & 3) * 2;

  for (int y = 0; y < 3; y++) {
    const __half* Wt = wT + y * 16384;  // [d][c], m=d rows, k=c unit
    load_conv16h<true, false, __half>(sAp, Wt + row * kC + khalf, 1, nullptr);
    __syncthreads();

    float acc[4][4][4];
#pragma unroll
    for (int i = 0; i < 4; i++)
#pragma unroll
      for (int j = 0; j < 4; j++)
#pragma unroll
        for (int c = 0; c < 4; c++) acc[i][j][c] = 0.f;

    for (int c = 0; c < 4; c++) {
      const uint32_t aBase = saA0 + (uint32_t)((c & 1) * kBufH * 2);
      const uint32_t bBase = saB0 + (uint32_t)(c * 64);  // +c*32 halves
#pragma unroll
      for (int ks = 0; ks < 2; ks++)
        warp_mma_step_h(acc, aBase, bBase, ks, kWnSH);
      if (c + 1 < 4) {
        const int nb = (c + 1) & 1;
        load_conv16h<true, false, __half>(sAp + nb * kBufH,
                                          Wt + row * kC + (c + 1) * 32 + khalf, 1,
                                          nullptr);
      }
      __syncthreads();
    }

    __half* C = ((y == 0) ? q : (y == 1) ? k : v) + zoff;
#pragma unroll
    for (int im = 0; im < 4; im++) {
      int m0 = wm + im * 16 + g;
      int m1 = m0 + 8;
      float bm0 = biasS[y][m0], bm1 = biasS[y][m1];
#pragma unroll
      for (int in = 0; in < 4; in++) {
        int n0 = wn + in * 8 + t2;
        int n1 = n0 + 1;
        C[(long)n0 * ((long)kH * kC) + m0] = __float2half_rn(acc[im][in][0] + bm0);
        C[(long)n1 * ((long)kH * kC) + m0] = __float2half_rn(acc[im][in][1] + bm0);
        C[(long)n0 * ((long)kH * kC) + m1] = __float2half_rn(acc[im][in][2] + bm1);
        C[(long)n1 * ((long)kH * kC) + m1] = __float2half_rn(acc[im][in][3] + bm1);
      }
    }
  }
}

template <bool AKC, bool BKC, bool NORM, bool EEPI, typename TA, typename TB, typename TC>
__global__ __launch_bounds__(256, 2) void gemm_gen(
    const TA* __restrict__ A, int a_div, long a_so, long a_si, long sAm, long sAk,
    const TB* __restrict__ Bp, int b_div, long b_so, long b_si, long sBn, long sBk,
    TC* __restrict__ Cp, int c_div, long c_so, long c_si, long sCn,
    const float* __restrict__ nrm_base, int nrm_div,
    const float* __restrict__ bias_m, const float* __restrict__ bias_n,
    float alpha, int K) {
  const int z = blockIdx.z, bx = blockIdx.x, by = blockIdx.y;
  A += (long)(z / a_div) * a_so + (long)(z % a_div) * a_si + (long)bx * 128 * sAm;
  Bp += (long)(z / b_div) * b_so + (long)(z % b_div) * b_si + (long)by * 128 * sBn;
  Cp += (long)(z / c_div) * c_so + (long)(z % c_div) * c_si + (long)bx * 128 +
        (long)by * 128 * sCn;
  const float* nrm = nullptr;
  if (NORM) nrm = nrm_base + (long)(z / nrm_div) * kCC + (long)bx * 128 * sAm;
  gemm_body<AKC, BKC, NORM, EEPI, TA, TB, TC>(
      A, sAm, sAk, Bp, sBn, sBk, Cp, sCn, nrm,
      bias_m ? bias_m + bx * 128 : nullptr,
      bias_n ? bias_n + by * 128 : nullptr, alpha, K);
}

// Fused pass4+pass5 per z=(b,w). GEMM1: A = s (fp16, d unit) * inv,
// B = WnT (fp16, d unit) -> wn in smem (fp16). GEMM2: A = v, B = wn smem.
__global__ __launch_bounds__(256, 2) void gemm_p45(
    const __half* __restrict__ s, const __half* __restrict__ wnT,
    const float* __restrict__ inv, const __half* __restrict__ v,
    const float* __restrict__ bn, __half* __restrict__ m5) {
  extern __shared__ __half dynH[];
  __half* const SA = dynH;
  __half* const SB = dynH + 2 * kBufH;
  __half* const WNS = dynH + 2 * kBufH;  // alias of SB region (+ extension)
  __shared__ float bnS[128];

  const int tid = threadIdx.x;
  const int lane = tid & 31, wid = tid >> 5;
  const int wm = (wid & 1) * 64, wn = (wid >> 1) * 32;
  const int row = tid >> 1, khalf = (tid & 1) * 16;
  const int z = blockIdx.z;
  const int b = z >> 7;  // z = b*kW + w

  if (tid < 128) bnS[tid] = bn[tid];

  // s layout (B,W,C,D): A[m=c stride kC, k=d unit]; inv (B,C,D) matches.
  const __half* Arow1 = s + (long)z * kCC + (long)row * kC + khalf;
  const float* Nrow1 = inv + (long)b * kCC + (long)row * kC + khalf;
  const __half* Brow1 = wnT + (long)row * kC + khalf;  // WnT [e][d], k=d unit
  __half* const sAp = SA + row * kLdsH + khalf;
  __half* const sBp = SB + row * kLdsH + khalf;

  const uint32_t saA0 = smem_u32(SA) + (uint32_t)(wm * kLdsH * 2) + a4_off_h(lane, kLdsH);
  const uint32_t saB0 = smem_u32(SB) + (uint32_t)(wn * kLdsH * 2) + b4_off_h(lane, kLdsH);

  load_conv16h<true, true, __half>(sAp, Arow1, 1, Nrow1);
  load_conv16h<true, false, __half>(sBp, Brow1, 1, nullptr);
  __syncthreads();

  float acc[4][4][4];
#pragma unroll
  for (int i = 0; i < 4; i++)
#pragma unroll
    for (int j = 0; j < 4; j++)
#pragma unroll
      for (int c = 0; c < 4; c++) acc[i][j][c] = 0.f;

  for (int c = 0; c < 4; c++) {
    const uint32_t stg = (uint32_t)((c & 1) * kBufH * 2);
#pragma unroll
    for (int ks = 0; ks < 2; ks++)
      warp_mma_step_h(acc, saA0 + stg, saB0 + stg, ks, kLdsH);
    if (c + 1 < 4) {
      const int nb = (c + 1) & 1;
      const long ko = (long)(c + 1) * 32;
      load_conv16h<true, true, __half>(sAp + nb * kBufH, Arow1 + ko, 1, Nrow1 + ko);
      load_conv16h<true, false, __half>(sBp + nb * kBufH, Brow1 + ko, 1, nullptr);
    }
    __syncthreads();
  }

  // Epilogue1: wn tile -> WNS[c*kWnSH + e] (fp16), +bn[e].
  const int g = lane >> 2, t2 = (lane & 3) * 2;
#pragma unroll
  for (int im = 0; im < 4; im++) {
    int m0 = wm + im * 16 + g;
    int m1 = m0 + 8;
#pragma unroll
    for (int in = 0; in < 4; in++) {
      int n0 = wn + in * 8 + t2;
      int n1 = n0 + 1;
      WNS[m0 * kWnSH + n0] = __float2half_rn(acc[im][in][0] + bnS[n0]);
      WNS[m0 * kWnSH + n1] = __float2half_rn(acc[im][in][1] + bnS[n1]);
      WNS[m1 * kWnSH + n0] = __float2half_rn(acc[im][in][2] + bnS[n0]);
      WNS[m1 * kWnSH + n1] = __float2half_rn(acc[im][in][3] + bnS[n1]);
    }
  }
  __syncthreads();

  // GEMM2: A[m=h, k=e] = v[z, h, e] (fp16, k unit stride); B from WNS.
  const __half* vz = v + (long)z * kH * kC;
  __half* const mz = m5 + (long)z * kC * kH;
  const uint32_t saB2 = smem_u32(WNS) + (uint32_t)(wn * kWnSH * 2) + b4_off_h(lane, kWnSH);

  for (int hh = 0; hh < 2; hh++) {
    const __half* Arow2 = vz + (long)(hh * 128 + row) * kC + khalf;
    load_conv16h<true, false, __half>(sAp, Arow2, 1, nullptr);
    __syncthreads();

#pragma unroll
    for (int i = 0; i < 4; i++)
#pragma unroll
      for (int j = 0; j < 4; j++)
#pragma unroll
        for (int c = 0; c < 4; c++) acc[i][j][c] = 0.f;

    for (int c = 0; c < 4; c++) {
      const uint32_t aBase = saA0 + (uint32_t)((c & 1) * kBufH * 2);
      const uint32_t bBase = saB2 + (uint32_t)(c * 64);  // c*32 halves
#pragma unroll
      for (int ks = 0; ks < 2; ks++)
        warp_mma_step_h(acc, aBase, bBase, ks, kWnSH);
      if (c + 1 < 4) {
        const int nb = (c + 1) & 1;
        load_conv16h<true, false, __half>(sAp + nb * kBufH, Arow2 + (c + 1) * 32, 1,
                                          nullptr);
      }
      __syncthreads();
    }

#pragma unroll
    for (int im = 0; im < 4; im++) {
      int m0 = hh * 128 + wm + im * 16 + g;
      int m1 = m0 + 8;
#pragma unroll
      for (int in = 0; in < 4; in++) {
        int n0 = wn + in * 8 + t2;
        int n1 = n0 + 1;
        mz[(long)n0 * kH + m0] = __float2half_rn(acc[im][in][0]);
        mz[(long)n1 * kH + m0] = __float2half_rn(acc[im][in][1]);
        mz[(long)n0 * kH + m1] = __float2half_rn(acc[im][in][2]);
        mz[(long)n1 * kH + m1] = __float2half_rn(acc[im][in][3]);
      }
    }
  }
}

// Per-(b,c,d) reciprocal of sum over w of exp(scores) stored in s (B,W,C,D).
__global__ __launch_bounds__(256) void softmax_sum(const __half* __restrict__ s,
                                                   float* __restrict__ inv) {
  long t = (long)blockIdx.x * blockDim.x + threadIdx.x;  // < B*C*C
  int b = (int)(t / kCC);
  int r = (int)(t % kCC);
  const __half* p = s + (long)b * kW * kCC + r;
  float l = 0.f;
#pragma unroll 8
  for (int w = 0; w < kW; w++) l += __half2float(p[(long)w * kCC]);
  inv[t] = 1.f / l;
}

// Transpose m5 (B,W,C,H) -> m6 (B,H,C,W), fp16.
__global__ __launch_bounds__(256) void trans_wh(const __half* __restrict__ in,
                                                __half* __restrict__ out) {
  __shared__ unsigned short tile[32][34];
  int bc = blockIdx.z;
  int b = bc / kC, c = bc % kC;
  long ibase = (long)b * kW * kC * kH + (long)c * kH;
  long obase = (long)b * kH * kC * kW + (long)c * kW;
  int w0 = blockIdx.x * 32, h0 = blockIdx.y * 32;
  int txl = threadIdx.x;
  const unsigned short* inu = reinterpret_cast<const unsigned short*>(in);
  unsigned short* outu = reinterpret_cast<unsigned short*>(out);
#pragma unroll
  for (int i = threadIdx.y; i < 32; i += 8)
    tile[i][txl] = inu[ibase + (long)(w0 + i) * (kC * kH) + h0 + txl];
  __syncthreads();
#pragma unroll
  for (int i = threadIdx.y; i < 32; i += 8)
    outu[obase + (long)(h0 + i) * (kC * kW) + w0 + txl] = tile[txl][i];
}

extern "C" void kernel_launch(void* const* d_in, const int* in_sizes, int n_in,
                              void* d_out, int out_size) {
  (void)in_sizes; (void)n_in; (void)out_size;
  const float* x  = (const float*)d_in[0];
  const float* Wq = (const float*)d_in[1];
  const float* bq = (const float*)d_in[2];
  const float* Wk = (const float*)d_in[3];
  const float* bk = (const float*)d_in[4];
  const float* Wv = (const float*)d_in[5];
  const float* bv = (const float*)d_in[6];
  const float* Wn = (const float*)d_in[7];
  const float* bn = (const float*)d_in[8];
  const float* Wo = (const float*)d_in[9];
  const float* bo = (const float*)d_in[10];
  float* out = (float*)d_out;

  __half *q, *k, *v, *s, *wT;
  float *inv;
  cudaGetSymbolAddress((void**)&q, g_q);
  cudaGetSymbolAddress((void**)&k, g_k);
  cudaGetSymbolAddress((void**)&v, g_v);
  cudaGetSymbolAddress((void**)&s, g_s);
  cudaGetSymbolAddress((void**)&inv, g_inv);
  cudaGetSymbolAddress((void**)&wT, g_wT);

  const long HC = (long)kH * kC;
  const long CW = (long)kC * kW;
  const long CC = kCC;

  // Pass 0: fp16 transposed weight cache.
  prep_w<<<dim3(64, 5), 256>>>(Wq, Wk, Wv, Wn, Wo);

  // Pass 1: QKV, one block per z; x tile staged once.
  const int dynQkv = (kWnHalves + 2 * kBufH) * 2;
  cudaFuncSetAttribute(gemm_qkv3, cudaFuncAttributeMaxDynamicSharedMemorySize, dynQkv);
  gemm_qkv3<<<dim3(1, 1, kB * kH), 256, dynQkv>>>(x, wT, bq, bk, bv, q, k, v);

  // Pass 2: s[b,w,c,d] = exp(sum_h k[h,d] q[h,c] / sqrt(W)). m=d, n=c, k=h.
  gemm_gen<false, false, false, true, __half, __half, __half>
      <<<dim3(1, 1, kB * kW), 256>>>(
      k, 1, HC, 0, 1, kC,
      q, 1, HC, 0, 1, kC,
      s, 1, CC, 0, kC,
      nullptr, 1, nullptr, nullptr, 0.08838834764831845f, kH);

  // Pass 3: softmax denominators (inv in (B,C,D)).
  softmax_sum<<<(int)((kB * CC) / 256), 256>>>(s, inv);

  // Pass 4+5 fused: wn in smem (fp16), m5 (B,W,C,H) fp16 into g_q.
  const int dynBytes = (2 * kBufH + kWnHalves) * 2;
  cudaFuncSetAttribute(gemm_p45, cudaFuncAttributeMaxDynamicSharedMemorySize, dynBytes);
  gemm_p45<<<dim3(1, 1, kB * kW), 256, dynBytes>>>(s, wT + 3 * 16384, inv, v, bn, q);

  // Pass 5.5: transpose m5 (B,W,C,H) -> m6 (B,H,C,W), fp16.
  trans_wh<<<dim3(kW / 32, kH / 32, kB * kC), dim3(32, 8)>>>(q, k);

  // Pass 6: out[b,h][w,o] = sum_c m6[c,w]*WoT[o,c] + bo[o]. m=w, n=o, k=c.
  gemm_gen<false, true, false, false, __half, __half, float>
      <<<dim3(1, 1, kB * kH), 256>>>(
      k, 1, CW, 0, 1, kW,
      wT + 4 * 16384, 1, 0, 0, kC, 1,
      out, 1, CW, 0, kW,
      nullptr, 1, nullptr, bo, 1.f, kC);
}

// round 17
// speedup vs baseline: 2.2879x; 1.1924x over previous
#include <cuda_runtime.h>
#include <cuda_fp16.h>
#include <cstdint>

namespace {
constexpr int kB = 16, kH = 256, kC = 128, kW = 128;
constexpr long kCC = (long)kC * kC;
constexpr long kCW = (long)kC * kW;  // 16384
}

// Scratch (device globals: allocation-free contract).
__device__ __align__(256) __half g_q[(size_t)kB * kW * kH * kC];  // q; reused m6 (B,H,W,C)
__device__ __align__(256) __half g_k[(size_t)kB * kW * kH * kC];  // k (B,W,H,C)
__device__ __align__(256) __half g_v[(size_t)kB * kW * kH * kC];  // v (B,W,H,C)
__device__ __align__(256) __half g_s[(size_t)kB * kW * kC * kC];  // exp(scores) (B,W,C,D)
__device__ float g_inv[(size_t)kB * kC * kC];                     // 1/sum_w exp (B,C,D)
// fp16 transposed weights: [0..2]=Wq/Wk/WvT [d][c], [3]=WnT [e][d], [4]=WoT [o][c].
__device__ __align__(256) __half g_wT[5 * 128 * 128];

__device__ __forceinline__ uint32_t smem_u32(const void* p) {
  uint32_t a;
  asm("{ .reg .u64 t; cvta.to.shared.u64 t, %1; cvt.u32.u64 %0, t; }" : "=r"(a) : "l"(p));
  return a;
}

// exp on the FMA pipe; clamp +-11 so result fits fp16 (e^11 ~ 59874 < 65504).
__device__ __forceinline__ float fast_exp(float x) {
  x = fminf(fmaxf(x, -11.f), 11.f);
  float r = rintf(x * 1.44269504f);
  float f = fmaf(r, -0.6931471805599453f, x);
  float p = 1.f + f * (1.f + f * (0.5f + f * (0.16666667f +
                f * (0.041666667f + f * 0.0083333333f))));
  return p * __int_as_float(((int)r + 127) << 23);
}

// SMEM strides (halves). 40 / 136: every ldmatrix phase spans all 32 banks.
constexpr int kLdsH = 40;
constexpr int kBufH = 128 * kLdsH;      // halves per stage (5120)
constexpr int kWnSH = 136;              // resident-tile smem row stride (halves)
constexpr int kWnHalves = 128 * kWnSH;  // 17408

__device__ __forceinline__ uint32_t h2u(__half2 h) {
  return *reinterpret_cast<uint32_t*>(&h);
}

// Load 16 k-words of one row (float). KC=true: k unit stride (float4).
template <bool KC>
__device__ __forceinline__ void ldg16(float4 r[4], const float* __restrict__ p, long sK) {
  if (KC) {
#pragma unroll
    for (int i = 0; i < 4; i++) r[i] = reinterpret_cast<const float4*>(p)[i];
  } else {
#pragma unroll
    for (int i = 0; i < 4; i++) {
      r[i].x = p[(long)(i * 4 + 0) * sK];
      r[i].y = p[(long)(i * 4 + 1) * sK];
      r[i].z = p[(long)(i * 4 + 2) * sK];
      r[i].w = p[(long)(i * 4 + 3) * sK];
    }
  }
}

// Load 16 k-elements of one row, as fp16, store 32 bytes to smem.
template <bool KC, bool NORM, typename T>
__device__ __forceinline__ void load_conv16h(__half* __restrict__ dst,
                                             const T* __restrict__ src, long sK,
                                             const float* __restrict__ nsrc) {
  uint32_t w[8];
  if constexpr (sizeof(T) == 4) {
    float4 a[4], n[4];
    ldg16<KC>(a, reinterpret_cast<const float*>(src), sK);
    if (NORM) ldg16<KC>(n, nsrc, sK);
#pragma unroll
    for (int i = 0; i < 4; i++) {
      float4 v = a[i];
      if (NORM) { v.x *= n[i].x; v.y *= n[i].y; v.z *= n[i].z; v.w *= n[i].w; }
      w[2 * i + 0] = h2u(__floats2half2_rn(v.x, v.y));
      w[2 * i + 1] = h2u(__floats2half2_rn(v.z, v.w));
    }
  } else {
    if constexpr (KC) {
      const uint4* p = reinterpret_cast<const uint4*>(src);
      uint4 u0 = p[0], u1 = p[1];
      w[0] = u0.x; w[1] = u0.y; w[2] = u0.z; w[3] = u0.w;
      w[4] = u1.x; w[5] = u1.y; w[6] = u1.z; w[7] = u1.w;
      if (NORM) {
        float4 n[4];
        ldg16<true>(n, nsrc, sK);
#pragma unroll
        for (int i = 0; i < 4; i++) {
          float2 f0 = __half22float2(*reinterpret_cast<__half2*>(&w[2 * i]));
          float2 f1 = __half22float2(*reinterpret_cast<__half2*>(&w[2 * i + 1]));
          w[2 * i + 0] = h2u(__floats2half2_rn(f0.x * n[i].x, f0.y * n[i].y));
          w[2 * i + 1] = h2u(__floats2half2_rn(f1.x * n[i].z, f1.y * n[i].w));
        }
      }
    } else {
      const unsigned short* p = reinterpret_cast<const unsigned short*>(src);
#pragma unroll
      for (int i = 0; i < 8; i++) {
        uint32_t lo = p[(long)(2 * i) * sK];
        uint32_t hi = p[(long)(2 * i + 1) * sK];
        w[i] = lo | (hi << 16);
      }
      if (NORM) {
#pragma unroll
        for (int i = 0; i < 8; i++) {
          float2 f = __half22float2(*reinterpret_cast<__half2*>(&w[i]));
          float n0 = nsrc[(long)(2 * i) * sK], n1 = nsrc[(long)(2 * i + 1) * sK];
          w[i] = h2u(__floats2half2_rn(f.x * n0, f.y * n1));
        }
      }
    }
  }
  const uint32_t d = smem_u32(dst);
  asm volatile("st.shared.v4.b32 [%0], {%1,%2,%3,%4};"
               :: "r"(d), "r"(w[0]), "r"(w[1]), "r"(w[2]), "r"(w[3]));
  asm volatile("st.shared.v4.b32 [%0], {%1,%2,%3,%4};"
               :: "r"(d + 16), "r"(w[4]), "r"(w[5]), "r"(w[6]), "r"(w[7]));
}

template <typename TC>
__device__ __forceinline__ void stC(TC* p, float v) {
  if constexpr (sizeof(TC) == 4) *reinterpret_cast<float*>(p) = v;
  else *reinterpret_cast<__half*>(p) = __float2half_rn(v);
}

__device__ __forceinline__ void ldsm_x4(uint32_t r[4], uint32_t addr) {
  asm volatile("ldmatrix.sync.aligned.m8n8.x4.shared.b16 {%0,%1,%2,%3}, [%4];"
               : "=r"(r[0]), "=r"(r[1]), "=r"(r[2]), "=r"(r[3]) : "r"(addr));
}

// Per-lane byte offsets for ldmatrix.x4 (SH = row stride in halves).
__device__ __forceinline__ uint32_t a4_off_h(int lane, int SH) {
  return (uint32_t)((((lane & 7) + ((lane >> 3) & 1) * 8) * SH * 2) + (lane >> 4) * 16);
}
__device__ __forceinline__ uint32_t b4_off_h(int lane, int SH) {
  return (uint32_t)((((lane & 7) + ((lane >> 4) & 1) * 8) * SH * 2) +
                    ((lane >> 3) & 1) * 16);
}

__device__ __forceinline__ void mma_f16(float acc[4], const uint32_t a[4],
                                        const uint32_t b[2]) {
  asm volatile(
      "mma.sync.aligned.m16n8k16.row.col.f32.f16.f16.f32 "
      "{%0,%1,%2,%3}, {%4,%5,%6,%7}, {%8,%9}, {%0,%1,%2,%3};"
      : "+f"(acc[0]), "+f"(acc[1]), "+f"(acc[2]), "+f"(acc[3])
      : "r"(a[0]), "r"(a[1]), "r"(a[2]), "r"(a[3]), "r"(b[0]), "r"(b[1]));
}

// One K=16 step of the 64x32 warp tile: 4 A ldsm.x4, 2 B ldsm.x4, 16 MMAs.
__device__ __forceinline__ void warp_mma_step_h(float acc[4][4][4], uint32_t aBase,
                                                uint32_t bBase, int ks, int strideBh) {
  uint32_t af[4][4], bt0[4], bt1[4];
#pragma unroll
  for (int im = 0; im < 4; im++)
    ldsm_x4(af[im], aBase + (uint32_t)(im * 16 * kLdsH * 2 + ks * 32));
  ldsm_x4(bt0, bBase + (uint32_t)(ks * 32));
  ldsm_x4(bt1, bBase + (uint32_t)(16 * strideBh * 2 + ks * 32));
  uint32_t bf[4][2] = {{bt0[0], bt0[1]}, {bt0[2], bt0[3]},
                       {bt1[0], bt1[1]}, {bt1[2], bt1[3]}};
#pragma unroll
  for (int im = 0; im < 4; im++)
#pragma unroll
    for (int in = 0; in < 4; in++) mma_f16(acc[im][in], af[im], bf[in]);
}

// Weight prep: g_wT[m] = transpose(W_m) in fp16. m 0..4.
__global__ __launch_bounds__(256) void prep_w(
    const float* __restrict__ Wq, const float* __restrict__ Wk,
    const float* __restrict__ Wv, const float* __restrict__ Wn,
    const float* __restrict__ Wo) {
  int t = blockIdx.x * 256 + threadIdx.x;  // 0..16383
  int m = blockIdx.y;
  const float* src = (m == 0) ? Wq : (m == 1) ? Wk : (m == 2) ? Wv : (m == 3) ? Wn : Wo;
  int r = t >> 7, c = t & 127;
  g_wT[m * 16384 + t] = __float2half_rn(src[c * 128 + r]);
}

// Core 128x128 GEMM body via mma.sync fp16 (fp32 accumulate).
template <bool AKC, bool BKC, bool NORM, bool EEPI, typename TA, typename TB, typename TC>
__device__ __forceinline__ void gemm_body(
    const TA* __restrict__ A, long sAm, long sAk,
    const TB* __restrict__ Bp, long sBn, long sBk,
    TC* __restrict__ Cp, long sCn,
    const float* __restrict__ nrm,
    const float* __restrict__ bias_m, const float* __restrict__ bias_n,
    float alpha, int K) {
  __shared__ __half As[2 * kBufH];
  __shared__ __half Bs[2 * kBufH];
  __shared__ float bmS[128], bnS[128];

  const int tid = threadIdx.x;
  const int lane = tid & 31, wid = tid >> 5;
  const int wm = (wid & 1) * 64, wn = (wid >> 1) * 32;
  const int row = tid >> 1, khalf = (tid & 1) * 16;

  if (!EEPI && tid < 128) {
    bmS[tid] = bias_m ? bias_m[tid] : 0.f;
    bnS[tid] = bias_n ? bias_n[tid] : 0.f;
  }

  const TA* Arow = A + (long)row * sAm + (long)khalf * sAk;
  const TB* Brow = Bp + (long)row * sBn + (long)khalf * sBk;
  const float* Nrow = NORM ? nrm + (long)row * sAm + (long)khalf * sAk : nullptr;
  __half* const sA = As + row * kLdsH + khalf;
  __half* const sB = Bs + row * kLdsH + khalf;

  const uint32_t saA0 = smem_u32(As) + (uint32_t)(wm * kLdsH * 2) + a4_off_h(lane, kLdsH);
  const uint32_t saB0 = smem_u32(Bs) + (uint32_t)(wn * kLdsH * 2) + b4_off_h(lane, kLdsH);

  load_conv16h<AKC, NORM, TA>(sA, Arow, sAk, Nrow);
  load_conv16h<BKC, false, TB>(sB, Brow, sBk, nullptr);
  __syncthreads();

  float acc[4][4][4];
#pragma unroll
  for (int i = 0; i < 4; i++)
#pragma unroll
    for (int j = 0; j < 4; j++)
#pragma unroll
      for (int c = 0; c < 4; c++) acc[i][j][c] = 0.f;

  const int nch = K >> 5;
  for (int c = 0; c < nch; c++) {
    const uint32_t stg = (uint32_t)((c & 1) * kBufH * 2);
#pragma unroll
    for (int ks = 0; ks < 2; ks++)
      warp_mma_step_h(acc, saA0 + stg, saB0 + stg, ks, kLdsH);
    if (c + 1 < nch) {
      const int nb = (c + 1) & 1;
      const long ko = (long)(c + 1) * 32;
      load_conv16h<AKC, NORM, TA>(sA + nb * kBufH, Arow + ko * sAk, sAk,
                                  NORM ? Nrow + ko * sAk : nullptr);
      load_conv16h<BKC, false, TB>(sB + nb * kBufH, Brow + ko * sBk, sBk, nullptr);
    }
    __syncthreads();
  }

  const int g = lane >> 2, t2 = (lane & 3) * 2;
#pragma unroll
  for (int im = 0; im < 4; im++) {
    int m0 = wm + im * 16 + g;
    int m1 = m0 + 8;
    float bm0 = EEPI ? 0.f : bmS[m0], bm1 = EEPI ? 0.f : bmS[m1];
#pragma unroll
    for (int in = 0; in < 4; in++) {
      int n0 = wn + in * 8 + t2;
      int n1 = n0 + 1;
      if (EEPI) {
        stC(Cp + (long)n0 * sCn + m0, fast_exp(alpha * acc[im][in][0]));
        stC(Cp + (long)n1 * sCn + m0, fast_exp(alpha * acc[im][in][1]));
        stC(Cp + (long)n0 * sCn + m1, fast_exp(alpha * acc[im][in][2]));
        stC(Cp + (long)n1 * sCn + m1, fast_exp(alpha * acc[im][in][3]));
      } else {
        float bn0 = bnS[n0], bn1 = bnS[n1];
        stC(Cp + (long)n0 * sCn + m0, alpha * acc[im][in][0] + bm0 + bn0);
        stC(Cp + (long)n1 * sCn + m0, alpha * acc[im][in][1] + bm0 + bn1);
        stC(Cp + (long)n0 * sCn + m1, alpha * acc[im][in][2] + bm1 + bn0);
        stC(Cp + (long)n1 * sCn + m1, alpha * acc[im][in][3] + bm1 + bn1);
      }
    }
  }
}

// QKV, one block per z=(b*H+h): x tile -> fp16 smem ONCE, then 3 sequential
// GEMMs (A = fp16 transposed weights, vector loads) against the resident B.
__global__ __launch_bounds__(256, 2) void gemm_qkv3(
    const float* __restrict__ x, const __half* __restrict__ wT,
    const float* __restrict__ bq, const float* __restrict__ bk,
    const float* __restrict__ bv,
    __half* __restrict__ q, __half* __restrict__ k, __half* __restrict__ v) {
  extern __shared__ __half dynH[];
  __half* const Bfull = dynH;             // 128 rows(w) x kWnSH (k=c)
  __half* const Ast = dynH + kWnHalves;   // 2 stages x 128 x kLdsH
  __shared__ float biasS[3][128];

  const int tid = threadIdx.x;
  const int lane = tid & 31, wid = tid >> 5;
  const int wm = (wid & 1) * 64, wn = (wid >> 1) * 32;
  const int row = tid >> 1, khalf = (tid & 1) * 16;
  const int z = blockIdx.z;

  if (tid < 128) {
    biasS[0][tid] = bq[tid];
    biasS[1][tid] = bk[tid];
    biasS[2][tid] = bv[tid];
  }

  // Fill B once: x[z] is [c][w]; B[n=w(row), k=c] -> strided fp32.
  const float* xz = x + (long)z * kC * kW;
#pragma unroll
  for (int c4 = 0; c4 < 4; c4++)
    load_conv16h<false, false, float>(Bfull + row * kWnSH + c4 * 32 + khalf,
                                      xz + row + (long)(c4 * 32 + khalf) * kW, kW,
                                      nullptr);
  __syncthreads();

  const uint32_t saB0 = smem_u32(Bfull) + (uint32_t)(wn * kWnSH * 2) + b4_off_h(lane, kWnSH);
  const uint32_t saA0 = smem_u32(Ast) + (uint32_t)(wm * kLdsH * 2) + a4_off_h(lane, kLdsH);
  __half* const sAp = Ast + row * kLdsH + khalf;

  const long zoff = (long)(z / kH) * ((long)kW * kH * kC) + (long)(z % kH) * kC;
  const int g = lane >> 2, t2 = (lane & 3) * 2;

  for (int y = 0; y < 3; y++) {
    const __half* Wt = wT + y * 16384;  // [d][c], m=d rows, k=c unit
    load_conv16h<true, false, __half>(sAp, Wt + row * kC + khalf, 1, nullptr);
    __syncthreads();

    float acc[4][4][4];
#pragma unroll
    for (int i = 0; i < 4; i++)
#pragma unroll
      for (int j = 0; j < 4; j++)
#pragma unroll
        for (int c = 0; c < 4; c++) acc[i][j][c] = 0.f;

    for (int c = 0; c < 4; c++) {
      const uint32_t aBase = saA0 + (uint32_t)((c & 1) * kBufH * 2);
      const uint32_t bBase = saB0 + (uint32_t)(c * 64);  // +c*32 halves
#pragma unroll
      for (int ks = 0; ks < 2; ks++)
        warp_mma_step_h(acc, aBase, bBase, ks, kWnSH);
      if (c + 1 < 4) {
        const int nb = (c + 1) & 1;
        load_conv16h<true, false, __half>(sAp + nb * kBufH,
                                          Wt + row * kC + (c + 1) * 32 + khalf, 1,
                                          nullptr);
      }
      __syncthreads();
    }

    __half* C = ((y == 0) ? q : (y == 1) ? k : v) + zoff;
#pragma unroll
    for (int im = 0; im < 4; im++) {
      int m0 = wm + im * 16 + g;
      int m1 = m0 + 8;
      float bm0 = biasS[y][m0], bm1 = biasS[y][m1];
#pragma unroll
      for (int in = 0; in < 4; in++) {
        int n0 = wn + in * 8 + t2;
        int n1 = n0 + 1;
        C[(long)n0 * ((long)kH * kC) + m0] = __float2half_rn(acc[im][in][0] + bm0);
        C[(long)n1 * ((long)kH * kC) + m0] = __float2half_rn(acc[im][in][1] + bm0);
        C[(long)n0 * ((long)kH * kC) + m1] = __float2half_rn(acc[im][in][2] + bm1);
        C[(long)n1 * ((long)kH * kC) + m1] = __float2half_rn(acc[im][in][3] + bm1);
      }
    }
  }
}

template <bool AKC, bool BKC, bool NORM, bool EEPI, typename TA, typename TB, typename TC>
__global__ __launch_bounds__(256, 2) void gemm_gen(
    const TA* __restrict__ A, int a_div, long a_so, long a_si, long sAm, long sAk,
    const TB* __restrict__ Bp, int b_div, long b_so, long b_si, long sBn, long sBk,
    TC* __restrict__ Cp, int c_div, long c_so, long c_si, long sCn,
    const float* __restrict__ nrm_base, int nrm_div,
    const float* __restrict__ bias_m, const float* __restrict__ bias_n,
    float alpha, int K) {
  const int z = blockIdx.z, bx = blockIdx.x, by = blockIdx.y;
  A += (long)(z / a_div) * a_so + (long)(z % a_div) * a_si + (long)bx * 128 * sAm;
  Bp += (long)(z / b_div) * b_so + (long)(z % b_div) * b_si + (long)by * 128 * sBn;
  Cp += (long)(z / c_div) * c_so + (long)(z % c_div) * c_si + (long)bx * 128 +
        (long)by * 128 * sCn;
  const float* nrm = nullptr;
  if (NORM) nrm = nrm_base + (long)(z / nrm_div) * kCC + (long)bx * 128 * sAm;
  gemm_body<AKC, BKC, NORM, EEPI, TA, TB, TC>(
      A, sAm, sAk, Bp, sBn, sBk, Cp, sCn, nrm,
      bias_m ? bias_m + bx * 128 : nullptr,
      bias_n ? bias_n + by * 128 : nullptr, alpha, K);
}

// Fused pass4+pass5 per z=(b,w). GEMM1: A = s (fp16, d unit) * inv,
// B = WnT (fp16, d unit) -> wn in smem (fp16). GEMM2: A = v, B = wn smem.
// GEMM2 epilogue writes m6 (B,H,W,C) directly (transpose folded in).
__global__ __launch_bounds__(256, 2) void gemm_p45(
    const __half* __restrict__ s, const __half* __restrict__ wnT,
    const float* __restrict__ inv, const __half* __restrict__ v,
    const float* __restrict__ bn, __half* __restrict__ m6) {
  extern __shared__ __half dynH[];
  __half* const SA = dynH;
  __half* const SB = dynH + 2 * kBufH;
  __half* const WNS = dynH + 2 * kBufH;  // alias of SB region (+ extension)
  __shared__ float bnS[128];

  const int tid = threadIdx.x;
  const int lane = tid & 31, wid = tid >> 5;
  const int wm = (wid & 1) * 64, wn = (wid >> 1) * 32;
  const int row = tid >> 1, khalf = (tid & 1) * 16;
  const int z = blockIdx.z;
  const int b = z >> 7, w = z & 127;  // z = b*kW + w

  if (tid < 128) bnS[tid] = bn[tid];

  // s layout (B,W,C,D): A[m=c stride kC, k=d unit]; inv (B,C,D) matches.
  const __half* Arow1 = s + (long)z * kCC + (long)row * kC + khalf;
  const float* Nrow1 = inv + (long)b * kCC + (long)row * kC + khalf;
  const __half* Brow1 = wnT + (long)row * kC + khalf;  // WnT [e][d], k=d unit
  __half* const sAp = SA + row * kLdsH + khalf;
  __half* const sBp = SB + row * kLdsH + khalf;

  const uint32_t saA0 = smem_u32(SA) + (uint32_t)(wm * kLdsH * 2) + a4_off_h(lane, kLdsH);
  const uint32_t saB0 = smem_u32(SB) + (uint32_t)(wn * kLdsH * 2) + b4_off_h(lane, kLdsH);

  load_conv16h<true, true, __half>(sAp, Arow1, 1, Nrow1);
  load_conv16h<true, false, __half>(sBp, Brow1, 1, nullptr);
  __syncthreads();

  float acc[4][4][4];
#pragma unroll
  for (int i = 0; i < 4; i++)
#pragma unroll
    for (int j = 0; j < 4; j++)
#pragma unroll
      for (int c = 0; c < 4; c++) acc[i][j][c] = 0.f;

  for (int c = 0; c < 4; c++) {
    const uint32_t stg = (uint32_t)((c & 1) * kBufH * 2);
#pragma unroll
    for (int ks = 0; ks < 2; ks++)
      warp_mma_step_h(acc, saA0 + stg, saB0 + stg, ks, kLdsH);
    if (c + 1 < 4) {
      const int nb = (c + 1) & 1;
      const long ko = (long)(c + 1) * 32;
      load_conv16h<true, true, __half>(sAp + nb * kBufH, Arow1 + ko, 1, Nrow1 + ko);
      load_conv16h<true, false, __half>(sBp + nb * kBufH, Brow1 + ko, 1, nullptr);
    }
    __syncthreads();
  }

  // Epilogue1: wn tile -> WNS[c*kWnSH + e] (fp16), +bn[e].
  const int g = lane >> 2, t2 = (lane & 3) * 2;
#pragma unroll
  for (int im = 0; im < 4; im++) {
    int m0 = wm + im * 16 + g;
    int m1 = m0 + 8;
#pragma unroll
    for (int in = 0; in < 4; in++) {
      int n0 = wn + in * 8 + t2;
      int n1 = n0 + 1;
      WNS[m0 * kWnSH + n0] = __float2half_rn(acc[im][in][0] + bnS[n0]);
      WNS[m0 * kWnSH + n1] = __float2half_rn(acc[im][in][1] + bnS[n1]);
      WNS[m1 * kWnSH + n0] = __float2half_rn(acc[im][in][2] + bnS[n0]);
      WNS[m1 * kWnSH + n1] = __float2half_rn(acc[im][in][3] + bnS[n1]);
    }
  }
  __syncthreads();

  // GEMM2: A[m=h, k=e] = v[z, h, e] (fp16, k unit stride); B from WNS.
  // Output m6 (B,H,W,C): addr = h*kCW + w*kC + c (half2 stores along c).
  const __half* vz = v + (long)z * kH * kC;
  __half2* const mz =
      reinterpret_cast<__half2*>(m6 + (long)b * kH * kCW + (long)w * kC);
  const uint32_t saB2 = smem_u32(WNS) + (uint32_t)(wn * kWnSH * 2) + b4_off_h(lane, kWnSH);

  for (int hh = 0; hh < 2; hh++) {
    const __half* Arow2 = vz + (long)(hh * 128 + row) * kC + khalf;
    load_conv16h<true, false, __half>(sAp, Arow2, 1, nullptr);
    __syncthreads();

#pragma unroll
    for (int i = 0; i < 4; i++)
#pragma unroll
      for (int j = 0; j < 4; j++)
#pragma unroll
        for (int c = 0; c < 4; c++) acc[i][j][c] = 0.f;

    for (int c = 0; c < 4; c++) {
      const uint32_t aBase = saA0 + (uint32_t)((c & 1) * kBufH * 2);
      const uint32_t bBase = saB2 + (uint32_t)(c * 64);  // c*32 halves
#pragma unroll
      for (int ks = 0; ks < 2; ks++)
        warp_mma_step_h(acc, aBase, bBase, ks, kWnSH);
      if (c + 1 < 4) {
        const int nb = (c + 1) & 1;
        load_conv16h<true, false, __half>(sAp + nb * kBufH, Arow2 + (c + 1) * 32, 1,
                                          nullptr);
      }
      __syncthreads();
    }

    // m = h, n = c. half2 along c (n0, n0+1 contiguous).
#pragma unroll
    for (int im = 0; im < 4; im++) {
      int m0 = hh * 128 + wm + im * 16 + g;
      int m1 = m0 + 8;
      long r0 = (long)m0 * (kCW / 2);
      long r1 = (long)m1 * (kCW / 2);
#pragma unroll
      for (int in = 0; in < 4; in++) {
        int nh = (wn + in * 8 + t2) >> 1;  // half2 index along c
        mz[r0 + nh] = __floats2half2_rn(acc[im][in][0], acc[im][in][1]);
        mz[r1 + nh] = __floats2half2_rn(acc[im][in][2], acc[im][in][3]);
      }
    }
  }
}

// Per-(b,c,d) reciprocal of sum over w of exp(scores) stored in s (B,W,C,D).
__global__ __launch_bounds__(256) void softmax_sum(const __half* __restrict__ s,
                                                   float* __restrict__ inv) {
  long t = (long)blockIdx.x * blockDim.x + threadIdx.x;  // < B*C*C
  int b = (int)(t / kCC);
  int r = (int)(t % kCC);
  const __half* p = s + (long)b * kW * kCC + r;
  float l = 0.f;
#pragma unroll 8
  for (int w = 0; w < kW; w++) l += __half2float(p[(long)w * kCC]);
  inv[t] = 1.f / l;
}

extern "C" void kernel_launch(void* const* d_in, const int* in_sizes, int n_in,
                              void* d_out, int out_size) {
  (void)in_sizes; (void)n_in; (void)out_size;
  const float* x  = (const float*)d_in[0];
  const float* Wq = (const float*)d_in[1];
  const float* bq = (const float*)d_in[2];
  const float* Wk = (const float*)d_in[3];
  const float* bk = (const float*)d_in[4];
  const float* Wv = (const float*)d_in[5];
  const float* bv = (const float*)d_in[6];
  const float* Wn = (const float*)d_in[7];
  const float* bn = (const float*)d_in[8];
  const float* Wo = (const float*)d_in[9];
  const float* bo = (const float*)d_in[10];
  float* out = (float*)d_out;

  __half *q, *k, *v, *s, *wT;
  float *inv;
  cudaGetSymbolAddress((void**)&q, g_q);
  cudaGetSymbolAddress((void**)&k, g_k);
  cudaGetSymbolAddress((void**)&v, g_v);
  cudaGetSymbolAddress((void**)&s, g_s);
  cudaGetSymbolAddress((void**)&inv, g_inv);
  cudaGetSymbolAddress((void**)&wT, g_wT);

  const long HC = (long)kH * kC;
  const long CC = kCC;

  // Pass 0: fp16 transposed weight cache.
  prep_w<<<dim3(64, 5), 256>>>(Wq, Wk, Wv, Wn, Wo);

  // Pass 1: QKV, one block per z; x tile staged once.
  const int dynQkv = (kWnHalves + 2 * kBufH) * 2;
  cudaFuncSetAttribute(gemm_qkv3, cudaFuncAttributeMaxDynamicSharedMemorySize, dynQkv);
  gemm_qkv3<<<dim3(1, 1, kB * kH), 256, dynQkv>>>(x, wT, bq, bk, bv, q, k, v);

  // Pass 2: s[b,w,c,d] = exp(sum_h k[h,d] q[h,c] / sqrt(W)). m=d, n=c, k=h.
  gemm_gen<false, false, false, true, __half, __half, __half>
      <<<dim3(1, 1, kB * kW), 256>>>(
      k, 1, HC, 0, 1, kC,
      q, 1, HC, 0, 1, kC,
      s, 1, CC, 0, kC,
      nullptr, 1, nullptr, nullptr, 0.08838834764831845f, kH);

  // Pass 3: softmax denominators (inv in (B,C,D)).
  softmax_sum<<<(int)((kB * CC) / 256), 256>>>(s, inv);

  // Pass 4+5 fused: wn in smem (fp16); m6 (B,H,W,C) fp16 into g_q directly.
  const int dynBytes = (2 * kBufH + kWnHalves) * 2;
  cudaFuncSetAttribute(gemm_p45, cudaFuncAttributeMaxDynamicSharedMemorySize, dynBytes);
  gemm_p45<<<dim3(1, 1, kB * kW), 256, dynBytes>>>(s, wT + 3 * 16384, inv, v, bn, q);

  // Pass 6: out[b,h][w,o] = sum_c m6[w,c]*WoT[o,c] + bo[o]. m=w, n=o, k=c.
  // m6 (B,H,W,C): A base = z*kCW, sAm = kC (w), sAk = 1 (c unit -> vector).
  gemm_gen<true, true, false, false, __half, __half, float>
      <<<dim3(1, 1, kB * kH), 256>>>(
      q, 1, kCW, 0, kC, 1,
      wT + 4 * 16384, 1, 0, 0, kC, 1,
      out, 1, kCW, 0, kW,
      nullptr, 1, nullptr, bo, 1.f, kC);
}